// round 12
// baseline (speedup 1.0000x reference)
#include <cuda_runtime.h>

#define NN 48
#define BATCH 4
#define CC 32
#define NSITES (BATCH*NN*NN*NN)
#define TSIZE  ((size_t)NSITES*CC)
#define NIMC   (BATCH*NN*NN*CC)
#define TOTSZ  (BATCH*NN*CC)
#define NPAIR  1176
#define NPB    4                 // pairs per k_conv block
#define PBLKS  (NPAIR/NPB)       // 294
#define THR    (NPB*NN)          // 192 threads

typedef unsigned long long u64t;

__device__ __forceinline__ u64t f2pack(float lo, float hi) {
    u64t r; asm("mov.b64 %0, {%1, %2};" : "=l"(r) : "f"(lo), "f"(hi)); return r;
}
__device__ __forceinline__ float2 f2unpack(u64t v) {
    float2 r; asm("mov.b64 {%0, %1}, %2;" : "=f"(r.x), "=f"(r.y) : "l"(v)); return r;
}
__device__ __forceinline__ void f2fma(u64t& d, u64t a, u64t b) {
    asm("fma.rn.f32x2 %0, %1, %2, %0;" : "+l"(d) : "l"(a), "l"(b));
}

__device__ float g_t[TSIZE];
__device__ float g_v[TSIZE];
__device__ float g_w[TSIZE];
__device__ float g_D [NIMC];      // [b][node][d][m]
__device__ float g_Cc[NIMC];      // [b][node][d][m]
__device__ float g_tot[3*TOTSZ];
__device__ float g_nv[BATCH*NN];
__device__ int   g_pairs[NPAIR];

// ---------- mask detect + node_valid + tot zero + pair table ----------
__global__ void k_mask(const void* __restrict__ mask) {
    __shared__ int smode;
    if (threadIdx.x == 0) {
        const unsigned char* mb = (const unsigned char*)mask;
        unsigned char b0 = mb[0], b1 = mb[1];
        int mode;
        if (b0 == 1 && b1 != 0) mode = 0;
        else if (b0 == 1)       mode = 1;
        else                    mode = 2;
        smode = mode;
    }
    __syncthreads();
    int p = threadIdx.x;
    if (p < BATCH*NN) {
        int b = p / NN, i = p % NN;
        size_t idx = (((size_t)b*NN + i)*NN + i)*NN + i;
        int mode = smode;
        float v;
        if (mode == 0)      v = ((const unsigned char*)mask)[idx] ? 1.f : 0.f;
        else if (mode == 1) v = ((const int*)mask)[idx] ? 1.f : 0.f;
        else                v = (((const float*)mask)[idx] != 0.f) ? 1.f : 0.f;
        g_nv[p] = v;
    }
    for (int q = threadIdx.x; q < 3*TOTSZ; q += 1024) g_tot[q] = 0.f;
    for (int q = threadIdx.x; q < NPAIR; q += 1024) {
        int i = 0, rem = q;
        while (rem >= NN - i) { rem -= NN - i; i++; }
        g_pairs[q] = (i << 8) | (i + rem);
    }
}

// ---------- t build ----------
__global__ __launch_bounds__(256) void k_build_t(const float* __restrict__ x) {
    int s = blockIdx.x * 256 + threadIdx.x;
    int m = s % NN, j = (s / NN) % NN, i = (s / (NN*NN)) % NN, b = s / (NN*NN*NN);
    float mv = g_nv[b*NN+i] * g_nv[b*NN+j] * g_nv[b*NN+m];
    const float4* xi = (const float4*)(x + (b*NN + i)*CC);
    const float4* xj = (const float4*)(x + (b*NN + j)*CC);
    const float4* xm = (const float4*)(x + (b*NN + m)*CC);
    float4* out = (float4*)(g_t + (size_t)s * CC);
#pragma unroll
    for (int q = 0; q < 8; q++) {
        float4 a = xi[q], c = xj[q], d = xm[q], r;
        r.x = a.x*c.x*d.x*mv; r.y = a.y*c.y*d.y*mv;
        r.z = a.z*c.z*d.z*mv; r.w = a.w*c.w*d.w*mv;
        out[q] = r;
    }
}

// ---------- rows/diag/cols + D/Cc contraction (transposed store) + atomic tot ----------
template<int COUT>
__global__ __launch_bounds__(256) void k_sums(const float* __restrict__ W, int layer) {
    __shared__ float sr[8][CC], sd[8][CC], sc[8][CC];
    int p = blockIdx.x * 256 + threadIdx.x;
    int c = p & 31;
    int m = (p >> 5) % NN;
    int a = (p / (32*NN)) % NN;
    int b = p / (32*NN*NN);
    int ls = threadIdx.x >> 5;

    const float* pr = g_t + ((((size_t)b*NN + a)*NN + 0)*NN + m)*CC + c;
    float r0=0.f, r1=0.f, r2=0.f, r3=0.f;
#pragma unroll
    for (int j = 0; j < NN; j += 4) {
        r0 += pr[(size_t)(j+0) * (NN*CC)];
        r1 += pr[(size_t)(j+1) * (NN*CC)];
        r2 += pr[(size_t)(j+2) * (NN*CC)];
        r3 += pr[(size_t)(j+3) * (NN*CC)];
    }
    float rowv  = (r0+r1+r2+r3) * (1.0f/NN);
    float diagv = pr[(size_t)a * (NN*CC)];

    const float* pc = g_t + ((((size_t)b*NN + 0)*NN + a)*NN + m)*CC + c;
    float s0=0.f, s1=0.f, s2=0.f, s3=0.f;
#pragma unroll
    for (int i = 0; i < NN; i += 4) {
        s0 += pc[(size_t)(i+0) * (NN*NN*CC)];
        s1 += pc[(size_t)(i+1) * (NN*NN*CC)];
        s2 += pc[(size_t)(i+2) * (NN*NN*CC)];
        s3 += pc[(size_t)(i+3) * (NN*NN*CC)];
    }
    float colv = (s0+s1+s2+s3) * (1.0f/NN);

    atomicAdd(&g_tot[layer*TOTSZ + (b*NN + m)*CC + c], rowv * (1.0f/NN));

    sr[ls][c] = rowv; sd[ls][c] = diagv; sc[ls][c] = colv;
    __syncthreads();

    if (c < COUT) {
        float accD = 0.f, accC = 0.f;
#pragma unroll 8
        for (int c2 = 0; c2 < CC; c2++) {
            accD += sd[ls][c2] * __ldg(W + (2*CC + c2)*COUT + c)
                  + sr[ls][c2] * __ldg(W + (3*CC + c2)*COUT + c);
            accC += sc[ls][c2] * __ldg(W + (4*CC + c2)*COUT + c);
        }
        size_t tidx = (((size_t)(b*NN + a))*COUT + c)*NN + m;
        g_D [tidx] = accD;
        g_Cc[tidx] = accC;
    }
}

// ---------- fused snconv: pair-aligned blocks + smem-staged I/O ----------
// block = 4 pairs x 48 m; tiles padded to 36-float rows (conflict-free .128 phases)
template<int COUT, bool FIN>
__global__ __launch_bounds__(THR, 3) void k_conv(const float* __restrict__ W,
                                                 const float* __restrict__ bb,
                                                 const float* __restrict__ Wv,
                                                 const float* __restrict__ bv,
                                                 const float* __restrict__ Ww,
                                                 const float* __restrict__ bw,
                                                 float* __restrict__ out_final,
                                                 int layer) {
    extern __shared__ __align__(16) float s[];
    constexpr int GOFF  = 2*CC*COUT;            // G table after W0|W1
    constexpr int GST   = COUT + 2;
    constexpr int TOFF  = GOFF + NN*GST;        // tiles after G
    constexpr int TOFF4 = TOFF/4;               // (TOFF multiple of 4)
    constexpr int TST4  = NN*9;                 // 432 f4 per padded tile
    float4* s4 = (float4*)s;
    __shared__ int spair[NPB];

    int tid = threadIdx.x;
    int bblk = blockIdx.x / PBLKS;
    int pblk = blockIdx.x % PBLKS;

    if (tid < NPB) spair[tid] = g_pairs[pblk*NPB + tid];
    __syncthreads();

    // W0|W1 into s[0 .. 2*CC*COUT)
    {
        const float4* W4 = (const float4*)W;
        for (int idx = tid; idx < (2*CC*COUT)/4; idx += THR)
            s4[idx] = W4[idx];
    }
    // G prologue
    {
        const float* tot = g_tot + layer*TOTSZ + bblk*(NN*CC);
        for (int idx = tid; idx < NN*COUT; idx += THR) {
            int mm = idx / COUT, d = idx % COUT;
            float a = __ldg(bb + d);
            const float* tr = tot + mm*CC;
#pragma unroll 8
            for (int c = 0; c < CC; c++)
                a += tr[c] * __ldg(W + (5*CC + c)*COUT + d);
            s[GOFF + mm*GST + d] = a;
        }
    }
    // coalesced t-tile load: 8 tiles (pair x {s0,s1}), 384 f4 each from contiguous gmem
    for (int idx4 = tid; idx4 < 8*384; idx4 += THR) {
        int t = idx4 / 384, q = idx4 % 384;
        int pij = spair[t >> 1];
        int ii = pij >> 8, jj = pij & 255;
        int a  = (t & 1) ? jj : ii;
        int bn = (t & 1) ? ii : jj;
        const float4* src = (const float4*)(g_t + ((((size_t)bblk*NN + a)*NN + bn)*NN)*CC);
        s4[TOFF4 + t*TST4 + (q >> 3)*9 + (q & 7)] = src[q];
    }
    __syncthreads();

    int p = tid / NN;
    int m = tid - p*NN;
    int pij = spair[p];
    int i = pij >> 8, j = pij & 255;

    int T0 = TOFF4 + (2*p)*TST4 + m*9;
    int T1 = T0 + TST4;

    u64t acc0[COUT/2], acc1[COUT/2];
#pragma unroll
    for (int q = 0; q < COUT/2; q++) { acc0[q] = 0ULL; acc1[q] = 0ULL; }

#pragma unroll 1
    for (int c0 = 0; c0 < CC; c0 += 8) {
        float ta[8], tb[8];
        float4 q4;
        q4 = s4[T0 + (c0>>2)];     ta[0]=q4.x; ta[1]=q4.y; ta[2]=q4.z; ta[3]=q4.w;
        q4 = s4[T0 + (c0>>2) + 1]; ta[4]=q4.x; ta[5]=q4.y; ta[6]=q4.z; ta[7]=q4.w;
        q4 = s4[T1 + (c0>>2)];     tb[0]=q4.x; tb[1]=q4.y; tb[2]=q4.z; tb[3]=q4.w;
        q4 = s4[T1 + (c0>>2) + 1]; tb[4]=q4.x; tb[5]=q4.y; tb[6]=q4.z; tb[7]=q4.w;
#pragma unroll
        for (int cc = 0; cc < 8; cc++) {
            int c = c0 + cc;
            u64t ta2 = f2pack(ta[cc], ta[cc]);
            u64t tb2 = f2pack(tb[cc], tb[cc]);
            const ulonglong2* w0p = (const ulonglong2*)(s + c*COUT);
            const ulonglong2* w1p = (const ulonglong2*)(s + CC*COUT + c*COUT);
#pragma unroll
            for (int q = 0; q < COUT/4; q++) {
                ulonglong2 w0 = w0p[q];
                ulonglong2 w1 = w1p[q];
                f2fma(acc0[2*q+0], ta2, w0.x);
                f2fma(acc0[2*q+1], ta2, w0.y);
                f2fma(acc0[2*q+0], tb2, w1.x);
                f2fma(acc0[2*q+1], tb2, w1.y);
                f2fma(acc1[2*q+0], tb2, w0.x);
                f2fma(acc1[2*q+1], tb2, w0.y);
                f2fma(acc1[2*q+0], ta2, w1.x);
                f2fma(acc1[2*q+1], ta2, w1.y);
            }
        }
    }

    // epilogue: coalesced D/C (m-major), padded G
    float mv = g_nv[bblk*NN+i] * g_nv[bblk*NN+j] * g_nv[bblk*NN+m];
    const float* Dib = g_D  + (((size_t)(bblk*NN + i))*COUT)*NN + m;
    const float* Djb = g_D  + (((size_t)(bblk*NN + j))*COUT)*NN + m;
    const float* Cib = g_Cc + (((size_t)(bblk*NN + i))*COUT)*NN + m;
    const float* Cjb = g_Cc + (((size_t)(bblk*NN + j))*COUT)*NN + m;
    const float* Gs  = s + GOFF + m*GST;
#pragma unroll
    for (int q = 0; q < COUT/2; q++) {
        int d0 = 2*q, d1 = 2*q+1;
        float2 a0 = f2unpack(acc0[q]);
        float2 a1 = f2unpack(acc1[q]);
        float g0 = Gs[d0],        g1 = Gs[d1];
        float di0 = Dib[d0*NN],   di1 = Dib[d1*NN];
        float dj0 = Djb[d0*NN],   dj1 = Djb[d1*NN];
        float ci0 = Cib[d0*NN],   ci1 = Cib[d1*NN];
        float cj0 = Cjb[d0*NN],   cj1 = Cjb[d1*NN];
        a0.x = (a0.x + di0 + cj0 + g0) * mv;
        a0.y = (a0.y + di1 + cj1 + g1) * mv;
        a1.x = (a1.x + dj0 + ci0 + g0) * mv;
        a1.y = (a1.y + dj1 + ci1 + g1) * mv;
        acc0[q] = f2pack(a0.x, a0.y);
        acc1[q] = f2pack(a1.x, a1.y);
    }

    if (FIN) {
        // stage 16-float rows into tiles, then coalesced sweep to out
        __syncthreads();
        {
            u64t* d0 = (u64t*)s + (size_t)(TOFF4 + (2*p)*TST4 + m*9)*2;
            u64t* d1 = (u64t*)s + (size_t)(TOFF4 + (2*p+1)*TST4 + m*9)*2;
#pragma unroll
            for (int e = 0; e < COUT/2; e++) { d0[e] = acc0[e]; d1[e] = acc1[e]; }
        }
        __syncthreads();
        for (int idx4 = tid; idx4 < 8*(NN*COUT/4); idx4 += THR) {
            int t = idx4 / (NN*COUT/4), q = idx4 % (NN*COUT/4);
            int pj = spair[t >> 1];
            int ii = pj >> 8, jj = pj & 255;
            int a  = (t & 1) ? jj : ii;
            int bn = (t & 1) ? ii : jj;
            float4* dst = (float4*)(out_final + ((((size_t)bblk*NN + a)*NN + bn)*NN)*COUT);
            dst[q] = s4[TOFF4 + t*TST4 + (q/(COUT/4))*9 + (q % (COUT/4))];
        }
    } else {
        __syncthreads();
        // reload Wv|Ww over dead W0|W1: s[0,1024)=Wv, s[1024,2048)=Ww
        {
            const float4* Wv4 = (const float4*)Wv;
            const float4* Ww4 = (const float4*)Ww;
            for (int idx = tid; idx < 512; idx += THR)
                s4[idx] = (idx < 256) ? Wv4[idx] : Ww4[idx - 256];
        }
        __syncthreads();

#pragma unroll 1
        for (int pass = 0; pass < 2; pass++) {
            const int WF = pass ? (CC*CC) : 0;
            const float* bias = pass ? bw : bv;
            float* outg = pass ? g_w : g_v;
            if (pass) __syncthreads();       // tiles free after previous sweep
#pragma unroll 1
            for (int half = 0; half < 2; half++) {
                u64t p0[8], p1[8];
                const u64t* b2 = (const u64t*)(bias + half*16);
#pragma unroll
                for (int e = 0; e < 8; e++) { u64t bb2 = b2[e]; p0[e] = bb2; p1[e] = bb2; }
#pragma unroll 1
                for (int dq = 0; dq < COUT/2; dq++) {
                    float2 a0 = f2unpack(acc0[dq]);
                    float2 a1 = f2unpack(acc1[dq]);
                    u64t a0x = f2pack(a0.x, a0.x), a0y = f2pack(a0.y, a0.y);
                    u64t a1x = f2pack(a1.x, a1.x), a1y = f2pack(a1.y, a1.y);
                    const ulonglong2* r0 = (const ulonglong2*)(s + WF + (2*dq+0)*CC + half*16);
                    const ulonglong2* r1 = (const ulonglong2*)(s + WF + (2*dq+1)*CC + half*16);
#pragma unroll
                    for (int q = 0; q < 4; q++) {
                        ulonglong2 w0 = r0[q];
                        ulonglong2 w1 = r1[q];
                        f2fma(p0[2*q+0], a0x, w0.x); f2fma(p0[2*q+1], a0x, w0.y);
                        f2fma(p0[2*q+0], a0y, w1.x); f2fma(p0[2*q+1], a0y, w1.y);
                        f2fma(p1[2*q+0], a1x, w0.x); f2fma(p1[2*q+1], a1x, w0.y);
                        f2fma(p1[2*q+0], a1y, w1.x); f2fma(p1[2*q+1], a1y, w1.y);
                    }
                }
                u64t* d0 = (u64t*)s + (size_t)(TOFF4 + (2*p)*TST4 + m*9)*2 + half*8;
                u64t* d1 = (u64t*)s + (size_t)(TOFF4 + (2*p+1)*TST4 + m*9)*2 + half*8;
#pragma unroll
                for (int e = 0; e < 8; e++) { d0[e] = p0[e]; d1[e] = p1[e]; }
            }
            __syncthreads();
            // coalesced sweep: 8 tiles x 384 f4
            for (int idx4 = tid; idx4 < 8*384; idx4 += THR) {
                int t = idx4 / 384, q = idx4 % 384;
                int pj = spair[t >> 1];
                int ii = pj >> 8, jj = pj & 255;
                int a  = (t & 1) ? jj : ii;
                int bn = (t & 1) ? ii : jj;
                float4* dst = (float4*)(outg + ((((size_t)bblk*NN + a)*NN + bn)*NN)*CC);
                dst[q] = s4[TOFF4 + t*TST4 + (q >> 3)*9 + (q & 7)];
            }
        }
    }
}

// ---------- localconv: 16x16 site tiles, K-split x4, 256 threads ----------
#define LK 12
#define VS_FL (16*LK*32)
#define WS_J_STRIDE 109
#define WS_FL (16*WS_J_STRIDE*4)
#define WO_OFFL (VS_FL + WS_FL)
#define DS_BYTES ((WO_OFFL + 1024)*4)
#define ZST 34

__global__ __launch_bounds__(256) void k_local(const float* __restrict__ Wo,
                                               const float* __restrict__ bo) {
    extern __shared__ __align__(16) float sm[];
    float* vs = sm;
    float* ws = sm + VS_FL;
    float* wo = sm + WO_OFFL;
    float* zs = sm;

    int blk = blockIdx.x;
    int q9 = blk % 9;
    int it3 = q9 / 3, jt3 = q9 % 3;
    int m = (blk / 9) % NN, b = blk / (9*NN);
    int i0 = it3 * 16, j0 = jt3 * 16;
    int tid = threadIdx.x;

    ((float4*)wo)[tid] = __ldg(((const float4*)Wo) + tid);

    int ct = tid & 7, jt = (tid >> 3) & 7, it = tid >> 6;
    u64t acc[4][2][2];
#pragma unroll
    for (int r = 0; r < 4; r++)
#pragma unroll
        for (int d = 0; d < 2; d++) { acc[r][d][0] = 0ULL; acc[r][d][1] = 0ULL; }

#pragma unroll 1
    for (int kc = 0; kc < 4; kc++) {
        if (kc) __syncthreads();
        for (int idx = tid; idx < 16*LK*8; idx += 256) {
            int r = idx >> 3, c4 = idx & 7;
            int iiL = r / LK, k = r % LK;
            float4 val = *(const float4*)(g_v + ((((size_t)b*NN + i0+iiL)*NN + kc*LK + k)*NN + m)*CC + c4*4);
            *((float4*)vs + (iiL*LK + k)*8 + c4) = val;
        }
        for (int idx = tid; idx < 16*LK*8; idx += 256) {
            int r = idx >> 3, c4 = idx & 7;
            int jjL = r / LK, k = r % LK;
            float4 val = *(const float4*)(g_w + ((((size_t)b*NN + kc*LK + k)*NN + j0+jjL)*NN + m)*CC + c4*4);
            *((float4*)ws + jjL*WS_J_STRIDE + k*9 + c4) = val;
        }
        __syncthreads();

#pragma unroll 4
        for (int k = 0; k < LK; k++) {
            ulonglong2 v[4];
#pragma unroll
            for (int r = 0; r < 4; r++)
                v[r] = *((const ulonglong2*)vs + ((it*4+r)*LK + k)*8 + ct);
            ulonglong2 w[2];
#pragma unroll
            for (int d = 0; d < 2; d++)
                w[d] = *((const ulonglong2*)ws + (jt*2+d)*WS_J_STRIDE + k*9 + ct);
#pragma unroll
            for (int r = 0; r < 4; r++)
#pragma unroll
                for (int d = 0; d < 2; d++) {
                    f2fma(acc[r][d][0], v[r].x, w[d].x);
                    f2fma(acc[r][d][1], v[r].y, w[d].y);
                }
        }
    }
    __syncthreads();

#pragma unroll
    for (int r = 0; r < 4; r++)
#pragma unroll
        for (int d = 0; d < 2; d++) {
            int il = it*4 + r, jl = jt*2 + d;
            u64t* zp = (u64t*)(zs + (il*16 + jl)*ZST + ct*4);
            zp[0] = acc[r][d][0];
            zp[1] = acc[r][d][1];
        }
    __syncthreads();

    int site = tid;
    int il = site >> 4, jl = site & 15;
    int gi = i0 + il, gj = j0 + jl;
    u64t oa[16];
#pragma unroll
    for (int q = 0; q < 16; q++) oa[q] = 0ULL;
#pragma unroll 4
    for (int c = 0; c < 32; c++) {
        float zv = zs[site*ZST + c];
        u64t zv2 = f2pack(zv, zv);
        const ulonglong2* wrow = (const ulonglong2*)(wo + c*32);
#pragma unroll
        for (int q = 0; q < 8; q++) {
            ulonglong2 w = wrow[q];
            f2fma(oa[2*q+0], zv2, w.x);
            f2fma(oa[2*q+1], zv2, w.y);
        }
    }
    float mv = g_nv[b*NN+gi] * g_nv[b*NN+gj] * g_nv[b*NN+m];
    float* op = g_t + ((((size_t)b*NN + gi)*NN + gj)*NN + m)*CC;
#pragma unroll
    for (int q = 0; q < 8; q++) {
        float2 p0 = f2unpack(oa[2*q+0]);
        float2 p1 = f2unpack(oa[2*q+1]);
        float e0 = p0.x * (1.0f/NN) + __ldg(bo + 4*q+0);
        float e1 = p0.y * (1.0f/NN) + __ldg(bo + 4*q+1);
        float e2 = p1.x * (1.0f/NN) + __ldg(bo + 4*q+2);
        float e3 = p1.y * (1.0f/NN) + __ldg(bo + 4*q+3);
        e0 = (e0 > 0.f ? e0 : 0.f) * mv;
        e1 = (e1 > 0.f ? e1 : 0.f) * mv;
        e2 = (e2 > 0.f ? e2 : 0.f) * mv;
        e3 = (e3 > 0.f ? e3 : 0.f) * mv;
        *(float4*)(op + 4*q) = make_float4(e0, e1, e2, e3);
    }
}

// ---------- host ----------
extern "C" void kernel_launch(void* const* d_in, const int* in_sizes, int n_in,
                              void* d_out, int out_size) {
    (void)in_sizes; (void)n_in; (void)out_size;
    const float* x    = (const float*)d_in[0];
    const void*  mask = d_in[1];

    // dynamic smem sizes for k_conv
    const int SM_NF = (2*CC*32 + NN*34 + 8*NN*36) * 4;   // 70016 B
    const int SM_F  = (2*CC*16 + NN*18 + 8*NN*36) * 4;   // 62848 B
    cudaFuncSetAttribute(k_local, cudaFuncAttributeMaxDynamicSharedMemorySize, DS_BYTES);
    cudaFuncSetAttribute(k_conv<32,false>, cudaFuncAttributeMaxDynamicSharedMemorySize, SM_NF);
    cudaFuncSetAttribute(k_conv<16,true>,  cudaFuncAttributeMaxDynamicSharedMemorySize, SM_F);

    k_mask<<<1, 1024>>>(mask);
    k_build_t<<<NSITES/256, 256>>>(x);

    for (int l = 0; l < 2; l++) {
        const float* W  = (const float*)d_in[2 + 8*l];
        const float* bb = (const float*)d_in[3 + 8*l];
        const float* Wv = (const float*)d_in[4 + 8*l];
        const float* bv = (const float*)d_in[5 + 8*l];
        const float* Ww = (const float*)d_in[6 + 8*l];
        const float* bw = (const float*)d_in[7 + 8*l];
        const float* Wo = (const float*)d_in[8 + 8*l];
        const float* bo = (const float*)d_in[9 + 8*l];
        k_sums<32><<<NIMC/256, 256>>>(W, l);
        k_conv<32, false><<<BATCH*PBLKS, THR, SM_NF>>>(W, bb, Wv, bv, Ww, bw, nullptr, l);
        k_local<<<BATCH*NN*9, 256, DS_BYTES>>>(Wo, bo);
    }

    const float* Wf  = (const float*)d_in[18];
    const float* bf  = (const float*)d_in[19];
    k_sums<16><<<NIMC/256, 256>>>(Wf, 2);
    k_conv<16, true><<<BATCH*PBLKS, THR, SM_F>>>(Wf, bf, nullptr, nullptr, nullptr, nullptr, (float*)d_out, 2);
}

// round 13
// speedup vs baseline: 1.2106x; 1.2106x over previous
#include <cuda_runtime.h>
#include <cstdint>

#define NN 48
#define BATCH 4
#define CC 32
#define NSITES (BATCH*NN*NN*NN)
#define TSIZE  ((size_t)NSITES*CC)
#define NIMC   (BATCH*NN*NN*CC)
#define TOTSZ  (BATCH*NN*CC)
#define NPAIR  1176
#define PTH    (NPAIR*NN)
#define BPB    ((PTH + 255)/256)

typedef unsigned long long u64t;

__device__ __forceinline__ u64t f2pack(float lo, float hi) {
    u64t r; asm("mov.b64 %0, {%1, %2};" : "=l"(r) : "f"(lo), "f"(hi)); return r;
}
__device__ __forceinline__ float2 f2unpack(u64t v) {
    float2 r; asm("mov.b64 {%0, %1}, %2;" : "=f"(r.x), "=f"(r.y) : "l"(v)); return r;
}
__device__ __forceinline__ void f2fma(u64t& d, u64t a, u64t b) {
    asm("fma.rn.f32x2 %0, %1, %2, %0;" : "+l"(d) : "l"(a), "l"(b));
}
__device__ __forceinline__ uint32_t smem_u32(const void* p) {
    uint32_t a;
    asm("{ .reg .u64 t; cvta.to.shared.u64 t, %1; cvt.u32.u64 %0, t; }" : "=r"(a) : "l"(p));
    return a;
}
__device__ __forceinline__ void cpa16(uint32_t dst, const void* src) {
    asm volatile("cp.async.cg.shared.global [%0], [%1], 16;" :: "r"(dst), "l"(src) : "memory");
}
#define CP_COMMIT() asm volatile("cp.async.commit_group;" ::: "memory")
#define CP_WAIT(n)  asm volatile("cp.async.wait_group %0;" :: "n"(n) : "memory")

__device__ float g_t[TSIZE];
__device__ float g_v[TSIZE];
__device__ float g_w[TSIZE];
__device__ float g_D [NIMC];      // [b][node][d][m]
__device__ float g_Cc[NIMC];      // [b][node][d][m]
__device__ float g_tot[3*TOTSZ];
__device__ float g_nv[BATCH*NN];
__device__ int   g_pairs[NPAIR];

// ---------- mask detect + node_valid + tot zero + pair table ----------
__global__ void k_mask(const void* __restrict__ mask) {
    __shared__ int smode;
    if (threadIdx.x == 0) {
        const unsigned char* mb = (const unsigned char*)mask;
        unsigned char b0 = mb[0], b1 = mb[1];
        int mode;
        if (b0 == 1 && b1 != 0) mode = 0;
        else if (b0 == 1)       mode = 1;
        else                    mode = 2;
        smode = mode;
    }
    __syncthreads();
    int p = threadIdx.x;
    if (p < BATCH*NN) {
        int b = p / NN, i = p % NN;
        size_t idx = (((size_t)b*NN + i)*NN + i)*NN + i;
        int mode = smode;
        float v;
        if (mode == 0)      v = ((const unsigned char*)mask)[idx] ? 1.f : 0.f;
        else if (mode == 1) v = ((const int*)mask)[idx] ? 1.f : 0.f;
        else                v = (((const float*)mask)[idx] != 0.f) ? 1.f : 0.f;
        g_nv[p] = v;
    }
    for (int q = threadIdx.x; q < 3*TOTSZ; q += 1024) g_tot[q] = 0.f;
    for (int q = threadIdx.x; q < NPAIR; q += 1024) {
        int i = 0, rem = q;
        while (rem >= NN - i) { rem -= NN - i; i++; }
        g_pairs[q] = (i << 8) | (i + rem);
    }
}

// ---------- t build ----------
__global__ __launch_bounds__(256) void k_build_t(const float* __restrict__ x) {
    int s = blockIdx.x * 256 + threadIdx.x;
    int m = s % NN, j = (s / NN) % NN, i = (s / (NN*NN)) % NN, b = s / (NN*NN*NN);
    float mv = g_nv[b*NN+i] * g_nv[b*NN+j] * g_nv[b*NN+m];
    const float4* xi = (const float4*)(x + (b*NN + i)*CC);
    const float4* xj = (const float4*)(x + (b*NN + j)*CC);
    const float4* xm = (const float4*)(x + (b*NN + m)*CC);
    float4* out = (float4*)(g_t + (size_t)s * CC);
#pragma unroll
    for (int q = 0; q < 8; q++) {
        float4 a = xi[q], c = xj[q], d = xm[q], r;
        r.x = a.x*c.x*d.x*mv; r.y = a.y*c.y*d.y*mv;
        r.z = a.z*c.z*d.z*mv; r.w = a.w*c.w*d.w*mv;
        out[q] = r;
    }
}

// ---------- rows/diag/cols + D/Cc contraction (transposed store) + atomic tot ----------
template<int COUT>
__global__ __launch_bounds__(256) void k_sums(const float* __restrict__ W, int layer) {
    __shared__ float sr[8][CC], sd[8][CC], sc[8][CC];
    int p = blockIdx.x * 256 + threadIdx.x;
    int c = p & 31;
    int m = (p >> 5) % NN;
    int a = (p / (32*NN)) % NN;
    int b = p / (32*NN*NN);
    int ls = threadIdx.x >> 5;

    const float* pr = g_t + ((((size_t)b*NN + a)*NN + 0)*NN + m)*CC + c;
    float r0=0.f, r1=0.f, r2=0.f, r3=0.f;
#pragma unroll
    for (int j = 0; j < NN; j += 4) {
        r0 += pr[(size_t)(j+0) * (NN*CC)];
        r1 += pr[(size_t)(j+1) * (NN*CC)];
        r2 += pr[(size_t)(j+2) * (NN*CC)];
        r3 += pr[(size_t)(j+3) * (NN*CC)];
    }
    float rowv  = (r0+r1+r2+r3) * (1.0f/NN);
    float diagv = pr[(size_t)a * (NN*CC)];

    const float* pc = g_t + ((((size_t)b*NN + 0)*NN + a)*NN + m)*CC + c;
    float s0=0.f, s1=0.f, s2=0.f, s3=0.f;
#pragma unroll
    for (int i = 0; i < NN; i += 4) {
        s0 += pc[(size_t)(i+0) * (NN*NN*CC)];
        s1 += pc[(size_t)(i+1) * (NN*NN*CC)];
        s2 += pc[(size_t)(i+2) * (NN*NN*CC)];
        s3 += pc[(size_t)(i+3) * (NN*NN*CC)];
    }
    float colv = (s0+s1+s2+s3) * (1.0f/NN);

    atomicAdd(&g_tot[layer*TOTSZ + (b*NN + m)*CC + c], rowv * (1.0f/NN));

    sr[ls][c] = rowv; sd[ls][c] = diagv; sc[ls][c] = colv;
    __syncthreads();

    if (c < COUT) {
        float accD = 0.f, accC = 0.f;
#pragma unroll 8
        for (int c2 = 0; c2 < CC; c2++) {
            accD += sd[ls][c2] * __ldg(W + (2*CC + c2)*COUT + c)
                  + sr[ls][c2] * __ldg(W + (3*CC + c2)*COUT + c);
            accC += sc[ls][c2] * __ldg(W + (4*CC + c2)*COUT + c);
        }
        size_t tidx = (((size_t)(b*NN + a))*COUT + c)*NN + m;
        g_D [tidx] = accD;
        g_Cc[tidx] = accC;
    }
}

// ---------- fused snconv: transpose-pair per thread (R11 version) ----------
template<int COUT, bool FIN>
__global__ __launch_bounds__(256, 2) void k_conv(const float* __restrict__ W,
                                                 const float* __restrict__ bb,
                                                 const float* __restrict__ Wv,
                                                 const float* __restrict__ bv,
                                                 const float* __restrict__ Ww,
                                                 const float* __restrict__ bw,
                                                 float* __restrict__ out_final,
                                                 int layer) {
    constexpr int WFL = FIN ? (2*CC*COUT) : (2*CC*COUT + 2*CC*CC);
    constexpr int GST = COUT + 2;
    __shared__ __align__(16) float s[WFL + NN*GST];
    float4* s4 = (float4*)s;
    {
        const float4* W4 = (const float4*)W;
        if (FIN) {
            for (int idx = threadIdx.x; idx < WFL/4; idx += 256)
                s4[idx] = W4[idx];
        } else {
            const float4* Wv4 = (const float4*)Wv;
            const float4* Ww4 = (const float4*)Ww;
            for (int idx = threadIdx.x; idx < 1024; idx += 256) {
                float4 val;
                if (idx < 512)      val = W4[idx];
                else if (idx < 768) val = Wv4[idx - 512];
                else                val = Ww4[idx - 768];
                s4[idx] = val;
            }
        }
    }
    int bblk = blockIdx.x / BPB;
    const float* tot = g_tot + layer*TOTSZ + bblk*(NN*CC);
    for (int idx = threadIdx.x; idx < NN*COUT; idx += 256) {
        int mm = idx / COUT, d = idx % COUT;
        float a = __ldg(bb + d);
        const float* tr = tot + mm*CC;
#pragma unroll 8
        for (int c = 0; c < CC; c++)
            a += tr[c] * __ldg(W + (5*CC + c)*COUT + d);
        s[WFL + mm*GST + d] = a;
    }
    __syncthreads();

    int local = (blockIdx.x % BPB) * 256 + threadIdx.x;
    if (local >= PTH) return;
    int m  = local % NN;
    int pr = local / NN;
    int pij = g_pairs[pr];
    int i = pij >> 8, j = pij & 255;

    size_t s0 = (((size_t)bblk*NN + i)*NN + j)*NN + m;
    size_t s1 = (((size_t)bblk*NN + j)*NN + i)*NN + m;
    const float* tv0 = g_t + s0 * CC;
    const float* tv1 = g_t + s1 * CC;

    u64t acc0[COUT/2], acc1[COUT/2];
#pragma unroll
    for (int q = 0; q < COUT/2; q++) { acc0[q] = 0ULL; acc1[q] = 0ULL; }

#pragma unroll 1
    for (int c0 = 0; c0 < CC; c0 += 8) {
        float ta[8], tb[8];
        float4 q4;
        q4 = *(const float4*)(tv0 + c0);     ta[0]=q4.x; ta[1]=q4.y; ta[2]=q4.z; ta[3]=q4.w;
        q4 = *(const float4*)(tv0 + c0 + 4); ta[4]=q4.x; ta[5]=q4.y; ta[6]=q4.z; ta[7]=q4.w;
        q4 = *(const float4*)(tv1 + c0);     tb[0]=q4.x; tb[1]=q4.y; tb[2]=q4.z; tb[3]=q4.w;
        q4 = *(const float4*)(tv1 + c0 + 4); tb[4]=q4.x; tb[5]=q4.y; tb[6]=q4.z; tb[7]=q4.w;
#pragma unroll
        for (int cc = 0; cc < 8; cc++) {
            int c = c0 + cc;
            u64t ta2 = f2pack(ta[cc], ta[cc]);
            u64t tb2 = f2pack(tb[cc], tb[cc]);
            const ulonglong2* w0p = (const ulonglong2*)(s + c*COUT);
            const ulonglong2* w1p = (const ulonglong2*)(s + CC*COUT + c*COUT);
#pragma unroll
            for (int q = 0; q < COUT/4; q++) {
                ulonglong2 w0 = w0p[q];
                ulonglong2 w1 = w1p[q];
                f2fma(acc0[2*q+0], ta2, w0.x);
                f2fma(acc0[2*q+1], ta2, w0.y);
                f2fma(acc0[2*q+0], tb2, w1.x);
                f2fma(acc0[2*q+1], tb2, w1.y);
                f2fma(acc1[2*q+0], tb2, w0.x);
                f2fma(acc1[2*q+1], tb2, w0.y);
                f2fma(acc1[2*q+0], ta2, w1.x);
                f2fma(acc1[2*q+1], ta2, w1.y);
            }
        }
    }

    float mv = g_nv[bblk*NN+i] * g_nv[bblk*NN+j] * g_nv[bblk*NN+m];
    const float* Dib = g_D  + (((size_t)(bblk*NN + i))*COUT)*NN + m;
    const float* Djb = g_D  + (((size_t)(bblk*NN + j))*COUT)*NN + m;
    const float* Cib = g_Cc + (((size_t)(bblk*NN + i))*COUT)*NN + m;
    const float* Cjb = g_Cc + (((size_t)(bblk*NN + j))*COUT)*NN + m;
    const float* Gs  = s + WFL + m*GST;
#pragma unroll
    for (int q = 0; q < COUT/2; q++) {
        int d0 = 2*q, d1 = 2*q+1;
        float2 a0 = f2unpack(acc0[q]);
        float2 a1 = f2unpack(acc1[q]);
        float g0 = Gs[d0],        g1 = Gs[d1];
        float di0 = Dib[d0*NN],   di1 = Dib[d1*NN];
        float dj0 = Djb[d0*NN],   dj1 = Djb[d1*NN];
        float ci0 = Cib[d0*NN],   ci1 = Cib[d1*NN];
        float cj0 = Cjb[d0*NN],   cj1 = Cjb[d1*NN];
        a0.x = (a0.x + di0 + cj0 + g0) * mv;
        a0.y = (a0.y + di1 + cj1 + g1) * mv;
        a1.x = (a1.x + dj0 + ci0 + g0) * mv;
        a1.y = (a1.y + dj1 + ci1 + g1) * mv;
        acc0[q] = f2pack(a0.x, a0.y);
        acc1[q] = f2pack(a1.x, a1.y);
    }

    if (FIN) {
        ulonglong2* op0 = (ulonglong2*)(out_final + s0 * COUT);
        ulonglong2* op1 = (ulonglong2*)(out_final + s1 * COUT);
#pragma unroll
        for (int q = 0; q < COUT/4; q++) {
            op0[q] = make_ulonglong2(acc0[2*q], acc0[2*q+1]);
            op1[q] = make_ulonglong2(acc1[2*q], acc1[2*q+1]);
        }
    } else {
        const int WVF = 2048, WWF = 3072;
#pragma unroll 1
        for (int pass = 0; pass < 2; pass++) {
            const int WF = pass ? WWF : WVF;
            const float* bias = pass ? bw : bv;
            float* outg = pass ? g_w : g_v;
#pragma unroll 1
            for (int half = 0; half < 2; half++) {
                u64t p0[8], p1[8];
                const u64t* b2 = (const u64t*)(bias + half*16);
#pragma unroll
                for (int e = 0; e < 8; e++) { u64t bb2 = b2[e]; p0[e] = bb2; p1[e] = bb2; }
#pragma unroll 1
                for (int dq = 0; dq < COUT/2; dq++) {
                    float2 a0 = f2unpack(acc0[dq]);
                    float2 a1 = f2unpack(acc1[dq]);
                    u64t a0x = f2pack(a0.x, a0.x), a0y = f2pack(a0.y, a0.y);
                    u64t a1x = f2pack(a1.x, a1.x), a1y = f2pack(a1.y, a1.y);
                    const ulonglong2* r0 = (const ulonglong2*)(s + WF + (2*dq+0)*CC + half*16);
                    const ulonglong2* r1 = (const ulonglong2*)(s + WF + (2*dq+1)*CC + half*16);
#pragma unroll
                    for (int q = 0; q < 4; q++) {
                        ulonglong2 w0 = r0[q];
                        ulonglong2 w1 = r1[q];
                        f2fma(p0[2*q+0], a0x, w0.x); f2fma(p0[2*q+1], a0x, w0.y);
                        f2fma(p0[2*q+0], a0y, w1.x); f2fma(p0[2*q+1], a0y, w1.y);
                        f2fma(p1[2*q+0], a1x, w0.x); f2fma(p1[2*q+1], a1x, w0.y);
                        f2fma(p1[2*q+0], a1y, w1.x); f2fma(p1[2*q+1], a1y, w1.y);
                    }
                }
                ulonglong2* o0 = (ulonglong2*)(outg + s0*CC + half*16);
                ulonglong2* o1 = (ulonglong2*)(outg + s1*CC + half*16);
#pragma unroll
                for (int q = 0; q < 4; q++) {
                    o0[q] = make_ulonglong2(p0[2*q], p0[2*q+1]);
                    o1[q] = make_ulonglong2(p1[2*q], p1[2*q+1]);
                }
            }
        }
    }
}

// ---------- localconv: 16x16 tiles, cp.async double-buffered K pipeline ----------
#define LK 12
#define VS_FL (16*LK*32)                 // 6144 floats
#define WS_J_STRIDE 109
#define WS_FL (16*WS_J_STRIDE*4)         // 6976 floats
#define BUF_FL (VS_FL + WS_FL)           // 13120 floats per buffer
#define WO_OFFL (2*BUF_FL)               // 26240
#define DS_BYTES ((WO_OFFL + 1024)*4)    // 109056 B
#define ZST 34

__global__ __launch_bounds__(256) void k_local(const float* __restrict__ Wo,
                                               const float* __restrict__ bo) {
    extern __shared__ __align__(16) float sm[];
    float* wo = sm + WO_OFFL;
    float* zs = sm;                      // alias buf0 after pipeline done

    int blk = blockIdx.x;
    int q9 = blk % 9;
    int it3 = q9 / 3, jt3 = q9 % 3;
    int m = (blk / 9) % NN, b = blk / (9*NN);
    int i0 = it3 * 16, j0 = jt3 * 16;
    int tid = threadIdx.x;
    uint32_t smbase = smem_u32(sm);

    ((float4*)wo)[tid] = __ldg(((const float4*)Wo) + tid);

    // async load of chunk kc into buffer bi
    auto load_chunk = [&](int kc, int bi) {
        uint32_t vb = smbase + (bi*BUF_FL)*4;
        uint32_t wb = vb + VS_FL*4;
        for (int idx = tid; idx < 16*LK*8; idx += 256) {
            int r = idx >> 3, c4 = idx & 7;
            int iiL = r / LK, k = r % LK;
            const float* src = g_v + ((((size_t)b*NN + i0+iiL)*NN + kc*LK + k)*NN + m)*CC + c4*4;
            cpa16(vb + ((iiL*LK + k)*8 + c4)*16, src);
        }
        for (int idx = tid; idx < 16*LK*8; idx += 256) {
            int r = idx >> 3, c4 = idx & 7;
            int jjL = r / LK, k = r % LK;
            const float* src = g_w + ((((size_t)b*NN + kc*LK + k)*NN + j0+jjL)*NN + m)*CC + c4*4;
            cpa16(wb + (jjL*WS_J_STRIDE + k*9 + c4)*16, src);
        }
    };

    int ct = tid & 7, jt = (tid >> 3) & 7, it = tid >> 6;
    u64t acc[4][2][2];
#pragma unroll
    for (int r = 0; r < 4; r++)
#pragma unroll
        for (int d = 0; d < 2; d++) { acc[r][d][0] = 0ULL; acc[r][d][1] = 0ULL; }

    load_chunk(0, 0);
    CP_COMMIT();

#pragma unroll 1
    for (int kc = 0; kc < 4; kc++) {
        int bi = kc & 1;
        if (kc + 1 < 4) { load_chunk(kc + 1, (kc + 1) & 1); CP_COMMIT(); }
        if (kc + 1 < 4) { CP_WAIT(1); } else { CP_WAIT(0); }
        __syncthreads();

        const float* vs = sm + bi*BUF_FL;
        const float* ws = vs + VS_FL;
#pragma unroll 4
        for (int k = 0; k < LK; k++) {
            ulonglong2 v[4];
#pragma unroll
            for (int r = 0; r < 4; r++)
                v[r] = *((const ulonglong2*)vs + ((it*4+r)*LK + k)*8 + ct);
            ulonglong2 w[2];
#pragma unroll
            for (int d = 0; d < 2; d++)
                w[d] = *((const ulonglong2*)ws + (jt*2+d)*WS_J_STRIDE + k*9 + ct);
#pragma unroll
            for (int r = 0; r < 4; r++)
#pragma unroll
                for (int d = 0; d < 2; d++) {
                    f2fma(acc[r][d][0], v[r].x, w[d].x);
                    f2fma(acc[r][d][1], v[r].y, w[d].y);
                }
        }
        __syncthreads();   // compute done before buffer bi is refilled (iter kc+2)
    }

#pragma unroll
    for (int r = 0; r < 4; r++)
#pragma unroll
        for (int d = 0; d < 2; d++) {
            int il = it*4 + r, jl = jt*2 + d;
            u64t* zp = (u64t*)(zs + (il*16 + jl)*ZST + ct*4);
            zp[0] = acc[r][d][0];
            zp[1] = acc[r][d][1];
        }
    __syncthreads();

    int site = tid;
    int il = site >> 4, jl = site & 15;
    int gi = i0 + il, gj = j0 + jl;
    u64t oa[16];
#pragma unroll
    for (int q = 0; q < 16; q++) oa[q] = 0ULL;
#pragma unroll 4
    for (int c = 0; c < 32; c++) {
        float zv = zs[site*ZST + c];
        u64t zv2 = f2pack(zv, zv);
        const ulonglong2* wrow = (const ulonglong2*)(wo + c*32);
#pragma unroll
        for (int q = 0; q < 8; q++) {
            ulonglong2 w = wrow[q];
            f2fma(oa[2*q+0], zv2, w.x);
            f2fma(oa[2*q+1], zv2, w.y);
        }
    }
    float mv = g_nv[b*NN+gi] * g_nv[b*NN+gj] * g_nv[b*NN+m];
    float* op = g_t + ((((size_t)b*NN + gi)*NN + gj)*NN + m)*CC;
#pragma unroll
    for (int q = 0; q < 8; q++) {
        float2 p0 = f2unpack(oa[2*q+0]);
        float2 p1 = f2unpack(oa[2*q+1]);
        float e0 = p0.x * (1.0f/NN) + __ldg(bo + 4*q+0);
        float e1 = p0.y * (1.0f/NN) + __ldg(bo + 4*q+1);
        float e2 = p1.x * (1.0f/NN) + __ldg(bo + 4*q+2);
        float e3 = p1.y * (1.0f/NN) + __ldg(bo + 4*q+3);
        e0 = (e0 > 0.f ? e0 : 0.f) * mv;
        e1 = (e1 > 0.f ? e1 : 0.f) * mv;
        e2 = (e2 > 0.f ? e2 : 0.f) * mv;
        e3 = (e3 > 0.f ? e3 : 0.f) * mv;
        *(float4*)(op + 4*q) = make_float4(e0, e1, e2, e3);
    }
}

// ---------- host ----------
extern "C" void kernel_launch(void* const* d_in, const int* in_sizes, int n_in,
                              void* d_out, int out_size) {
    (void)in_sizes; (void)n_in; (void)out_size;
    const float* x    = (const float*)d_in[0];
    const void*  mask = d_in[1];

    cudaFuncSetAttribute(k_local, cudaFuncAttributeMaxDynamicSharedMemorySize, DS_BYTES);

    k_mask<<<1, 1024>>>(mask);
    k_build_t<<<NSITES/256, 256>>>(x);

    for (int l = 0; l < 2; l++) {
        const float* W  = (const float*)d_in[2 + 8*l];
        const float* bb = (const float*)d_in[3 + 8*l];
        const float* Wv = (const float*)d_in[4 + 8*l];
        const float* bv = (const float*)d_in[5 + 8*l];
        const float* Ww = (const float*)d_in[6 + 8*l];
        const float* bw = (const float*)d_in[7 + 8*l];
        const float* Wo = (const float*)d_in[8 + 8*l];
        const float* bo = (const float*)d_in[9 + 8*l];
        k_sums<32><<<NIMC/256, 256>>>(W, l);
        k_conv<32, false><<<BATCH*BPB, 256>>>(W, bb, Wv, bv, Ww, bw, nullptr, l);
        k_local<<<BATCH*NN*9, 256, DS_BYTES>>>(Wo, bo);
    }

    const float* Wf  = (const float*)d_in[18];
    const float* bf  = (const float*)d_in[19];
    k_sums<16><<<NIMC/256, 256>>>(Wf, 2);
    k_conv<16, true><<<BATCH*BPB, 256>>>(Wf, bf, nullptr, nullptr, nullptr, nullptr, (float*)d_out, 2);
}

// round 14
// speedup vs baseline: 1.2111x; 1.0004x over previous
#include <cuda_runtime.h>
#include <cstdint>

#define NN 48
#define BATCH 4
#define CC 32
#define NSITES (BATCH*NN*NN*NN)
#define TSIZE  ((size_t)NSITES*CC)
#define NIMC   (BATCH*NN*NN*CC)
#define TOTSZ  (BATCH*NN*CC)
#define NPAIR  1176
#define PTH    (NPAIR*NN)
#define BPB    ((PTH + 255)/256)

typedef unsigned long long u64t;

__device__ __forceinline__ u64t f2pack(float lo, float hi) {
    u64t r; asm("mov.b64 %0, {%1, %2};" : "=l"(r) : "f"(lo), "f"(hi)); return r;
}
__device__ __forceinline__ float2 f2unpack(u64t v) {
    float2 r; asm("mov.b64 {%0, %1}, %2;" : "=f"(r.x), "=f"(r.y) : "l"(v)); return r;
}
__device__ __forceinline__ void f2fma(u64t& d, u64t a, u64t b) {
    asm("fma.rn.f32x2 %0, %1, %2, %0;" : "+l"(d) : "l"(a), "l"(b));
}
__device__ __forceinline__ uint32_t smem_u32(const void* p) {
    uint32_t a;
    asm("{ .reg .u64 t; cvta.to.shared.u64 t, %1; cvt.u32.u64 %0, t; }" : "=r"(a) : "l"(p));
    return a;
}
__device__ __forceinline__ void cpa16(uint32_t dst, const void* src) {
    asm volatile("cp.async.cg.shared.global [%0], [%1], 16;" :: "r"(dst), "l"(src) : "memory");
}
#define CP_COMMIT() asm volatile("cp.async.commit_group;" ::: "memory")
#define CP_WAIT(n)  asm volatile("cp.async.wait_group %0;" :: "n"(n) : "memory")

__device__ float g_t[TSIZE];
__device__ float g_v[TSIZE];
__device__ float g_w[TSIZE];
__device__ float g_D [NIMC];      // [b][node][d][m]
__device__ float g_Cc[NIMC];      // [b][node][d][m]
__device__ float g_tot[3*TOTSZ];
__device__ float g_nv[BATCH*NN];
__device__ int   g_pairs[NPAIR];

// ---------- mask detect + node_valid + tot zero + pair table ----------
__global__ void k_mask(const void* __restrict__ mask) {
    __shared__ int smode;
    if (threadIdx.x == 0) {
        const unsigned char* mb = (const unsigned char*)mask;
        unsigned char b0 = mb[0], b1 = mb[1];
        int mode;
        if (b0 == 1 && b1 != 0) mode = 0;
        else if (b0 == 1)       mode = 1;
        else                    mode = 2;
        smode = mode;
    }
    __syncthreads();
    int p = threadIdx.x;
    if (p < BATCH*NN) {
        int b = p / NN, i = p % NN;
        size_t idx = (((size_t)b*NN + i)*NN + i)*NN + i;
        int mode = smode;
        float v;
        if (mode == 0)      v = ((const unsigned char*)mask)[idx] ? 1.f : 0.f;
        else if (mode == 1) v = ((const int*)mask)[idx] ? 1.f : 0.f;
        else                v = (((const float*)mask)[idx] != 0.f) ? 1.f : 0.f;
        g_nv[p] = v;
    }
    for (int q = threadIdx.x; q < 3*TOTSZ; q += 1024) g_tot[q] = 0.f;
    for (int q = threadIdx.x; q < NPAIR; q += 1024) {
        int i = 0, rem = q;
        while (rem >= NN - i) { rem -= NN - i; i++; }
        g_pairs[q] = (i << 8) | (i + rem);
    }
}

// ---------- t build (mask fast-path) ----------
__global__ __launch_bounds__(256) void k_build_t(const float* __restrict__ x) {
    int s = blockIdx.x * 256 + threadIdx.x;
    int m = s % NN, j = (s / NN) % NN, i = (s / (NN*NN)) % NN, b = s / (NN*NN*NN);
    float mv = g_nv[b*NN+i] * g_nv[b*NN+j] * g_nv[b*NN+m];
    float4* out = (float4*)(g_t + (size_t)s * CC);
    if (mv == 0.f) {
        float4 z = make_float4(0.f, 0.f, 0.f, 0.f);
#pragma unroll
        for (int q = 0; q < 8; q++) out[q] = z;
        return;
    }
    const float4* xi = (const float4*)(x + (b*NN + i)*CC);
    const float4* xj = (const float4*)(x + (b*NN + j)*CC);
    const float4* xm = (const float4*)(x + (b*NN + m)*CC);
#pragma unroll
    for (int q = 0; q < 8; q++) {
        float4 a = xi[q], c = xj[q], d = xm[q], r;
        r.x = a.x*c.x*d.x; r.y = a.y*c.y*d.y;
        r.z = a.z*c.z*d.z; r.w = a.w*c.w*d.w;
        out[q] = r;
    }
}

// ---------- rows/diag/cols + D/Cc (transposed) + atomic tot; warp-uniform skip ----------
template<int COUT>
__global__ __launch_bounds__(256) void k_sums(const float* __restrict__ W, int layer) {
    __shared__ float sr[8][CC], sd[8][CC], sc[8][CC];
    int p = blockIdx.x * 256 + threadIdx.x;
    int c = p & 31;
    int m = (p >> 5) % NN;
    int a = (p / (32*NN)) % NN;
    int b = p / (32*NN*NN);
    int ls = threadIdx.x >> 5;

    bool valid = (g_nv[b*NN+a] * g_nv[b*NN+m]) != 0.f;   // warp-uniform
    float rowv = 0.f, diagv = 0.f, colv = 0.f;

    if (valid) {
        const float* pr = g_t + ((((size_t)b*NN + a)*NN + 0)*NN + m)*CC + c;
        float r0=0.f, r1=0.f, r2=0.f, r3=0.f;
#pragma unroll
        for (int j = 0; j < NN; j += 4) {
            r0 += pr[(size_t)(j+0) * (NN*CC)];
            r1 += pr[(size_t)(j+1) * (NN*CC)];
            r2 += pr[(size_t)(j+2) * (NN*CC)];
            r3 += pr[(size_t)(j+3) * (NN*CC)];
        }
        rowv  = (r0+r1+r2+r3) * (1.0f/NN);
        diagv = pr[(size_t)a * (NN*CC)];

        const float* pc = g_t + ((((size_t)b*NN + 0)*NN + a)*NN + m)*CC + c;
        float s0=0.f, s1=0.f, s2=0.f, s3=0.f;
#pragma unroll
        for (int i = 0; i < NN; i += 4) {
            s0 += pc[(size_t)(i+0) * (NN*NN*CC)];
            s1 += pc[(size_t)(i+1) * (NN*NN*CC)];
            s2 += pc[(size_t)(i+2) * (NN*NN*CC)];
            s3 += pc[(size_t)(i+3) * (NN*NN*CC)];
        }
        colv = (s0+s1+s2+s3) * (1.0f/NN);

        atomicAdd(&g_tot[layer*TOTSZ + (b*NN + m)*CC + c], rowv * (1.0f/NN));
    }

    sr[ls][c] = rowv; sd[ls][c] = diagv; sc[ls][c] = colv;
    __syncthreads();

    if (c < COUT) {
        size_t tidx = (((size_t)(b*NN + a))*COUT + c)*NN + m;
        if (valid) {
            float accD = 0.f, accC = 0.f;
#pragma unroll 8
            for (int c2 = 0; c2 < CC; c2++) {
                accD += sd[ls][c2] * __ldg(W + (2*CC + c2)*COUT + c)
                      + sr[ls][c2] * __ldg(W + (3*CC + c2)*COUT + c);
                accC += sc[ls][c2] * __ldg(W + (4*CC + c2)*COUT + c);
            }
            g_D [tidx] = accD;
            g_Cc[tidx] = accC;
        } else {
            g_D [tidx] = 0.f;
            g_Cc[tidx] = 0.f;
        }
    }
}

// ---------- fused snconv: transpose-pair per thread + masked fast-path ----------
template<int COUT, bool FIN>
__global__ __launch_bounds__(256, 2) void k_conv(const float* __restrict__ W,
                                                 const float* __restrict__ bb,
                                                 const float* __restrict__ Wv,
                                                 const float* __restrict__ bv,
                                                 const float* __restrict__ Ww,
                                                 const float* __restrict__ bw,
                                                 float* __restrict__ out_final,
                                                 int layer) {
    constexpr int WFL = FIN ? (2*CC*COUT) : (2*CC*COUT + 2*CC*CC);
    constexpr int GST = COUT + 2;
    __shared__ __align__(16) float s[WFL + NN*GST];
    float4* s4 = (float4*)s;
    {
        const float4* W4 = (const float4*)W;
        if (FIN) {
            for (int idx = threadIdx.x; idx < WFL/4; idx += 256)
                s4[idx] = W4[idx];
        } else {
            const float4* Wv4 = (const float4*)Wv;
            const float4* Ww4 = (const float4*)Ww;
            for (int idx = threadIdx.x; idx < 1024; idx += 256) {
                float4 val;
                if (idx < 512)      val = W4[idx];
                else if (idx < 768) val = Wv4[idx - 512];
                else                val = Ww4[idx - 768];
                s4[idx] = val;
            }
        }
    }
    int bblk = blockIdx.x / BPB;
    const float* tot = g_tot + layer*TOTSZ + bblk*(NN*CC);
    for (int idx = threadIdx.x; idx < NN*COUT; idx += 256) {
        int mm = idx / COUT, d = idx % COUT;
        float a = __ldg(bb + d);
        const float* tr = tot + mm*CC;
#pragma unroll 8
        for (int c = 0; c < CC; c++)
            a += tr[c] * __ldg(W + (5*CC + c)*COUT + d);
        s[WFL + mm*GST + d] = a;
    }
    __syncthreads();

    int local = (blockIdx.x % BPB) * 256 + threadIdx.x;
    if (local >= PTH) return;
    int m  = local % NN;
    int pr = local / NN;
    int pij = g_pairs[pr];
    int i = pij >> 8, j = pij & 255;

    size_t s0 = (((size_t)bblk*NN + i)*NN + j)*NN + m;
    size_t s1 = (((size_t)bblk*NN + j)*NN + i)*NN + m;

    float mv = g_nv[bblk*NN+i] * g_nv[bblk*NN+j] * g_nv[bblk*NN+m];

    // ---- masked fast-path: snconv output is exactly 0 -> v=bv, w=bw (FIN: 0) ----
    if (mv == 0.f) {
        if (FIN) {
            ulonglong2 z = make_ulonglong2(0ULL, 0ULL);
            ulonglong2* op0 = (ulonglong2*)(out_final + s0 * COUT);
            ulonglong2* op1 = (ulonglong2*)(out_final + s1 * COUT);
#pragma unroll
            for (int q = 0; q < COUT/4; q++) { op0[q] = z; op1[q] = z; }
        } else {
            const ulonglong2* bv2 = (const ulonglong2*)bv;
            const ulonglong2* bw2 = (const ulonglong2*)bw;
            ulonglong2* v0 = (ulonglong2*)(g_v + s0*CC);
            ulonglong2* v1 = (ulonglong2*)(g_v + s1*CC);
            ulonglong2* w0 = (ulonglong2*)(g_w + s0*CC);
            ulonglong2* w1 = (ulonglong2*)(g_w + s1*CC);
#pragma unroll
            for (int q = 0; q < CC/4; q++) {
                ulonglong2 a = __ldg(bv2 + q);
                ulonglong2 b2 = __ldg(bw2 + q);
                v0[q] = a; v1[q] = a;
                w0[q] = b2; w1[q] = b2;
            }
        }
        return;
    }

    const float* tv0 = g_t + s0 * CC;
    const float* tv1 = g_t + s1 * CC;

    u64t acc0[COUT/2], acc1[COUT/2];
#pragma unroll
    for (int q = 0; q < COUT/2; q++) { acc0[q] = 0ULL; acc1[q] = 0ULL; }

#pragma unroll 1
    for (int c0 = 0; c0 < CC; c0 += 8) {
        float ta[8], tb[8];
        float4 q4;
        q4 = *(const float4*)(tv0 + c0);     ta[0]=q4.x; ta[1]=q4.y; ta[2]=q4.z; ta[3]=q4.w;
        q4 = *(const float4*)(tv0 + c0 + 4); ta[4]=q4.x; ta[5]=q4.y; ta[6]=q4.z; ta[7]=q4.w;
        q4 = *(const float4*)(tv1 + c0);     tb[0]=q4.x; tb[1]=q4.y; tb[2]=q4.z; tb[3]=q4.w;
        q4 = *(const float4*)(tv1 + c0 + 4); tb[4]=q4.x; tb[5]=q4.y; tb[6]=q4.z; tb[7]=q4.w;
#pragma unroll
        for (int cc = 0; cc < 8; cc++) {
            int c = c0 + cc;
            u64t ta2 = f2pack(ta[cc], ta[cc]);
            u64t tb2 = f2pack(tb[cc], tb[cc]);
            const ulonglong2* w0p = (const ulonglong2*)(s + c*COUT);
            const ulonglong2* w1p = (const ulonglong2*)(s + CC*COUT + c*COUT);
#pragma unroll
            for (int q = 0; q < COUT/4; q++) {
                ulonglong2 w0 = w0p[q];
                ulonglong2 w1 = w1p[q];
                f2fma(acc0[2*q+0], ta2, w0.x);
                f2fma(acc0[2*q+1], ta2, w0.y);
                f2fma(acc0[2*q+0], tb2, w1.x);
                f2fma(acc0[2*q+1], tb2, w1.y);
                f2fma(acc1[2*q+0], tb2, w0.x);
                f2fma(acc1[2*q+1], tb2, w0.y);
                f2fma(acc1[2*q+0], ta2, w1.x);
                f2fma(acc1[2*q+1], ta2, w1.y);
            }
        }
    }

    const float* Dib = g_D  + (((size_t)(bblk*NN + i))*COUT)*NN + m;
    const float* Djb = g_D  + (((size_t)(bblk*NN + j))*COUT)*NN + m;
    const float* Cib = g_Cc + (((size_t)(bblk*NN + i))*COUT)*NN + m;
    const float* Cjb = g_Cc + (((size_t)(bblk*NN + j))*COUT)*NN + m;
    const float* Gs  = s + WFL + m*GST;
#pragma unroll
    for (int q = 0; q < COUT/2; q++) {
        int d0 = 2*q, d1 = 2*q+1;
        float2 a0 = f2unpack(acc0[q]);
        float2 a1 = f2unpack(acc1[q]);
        float g0 = Gs[d0],        g1 = Gs[d1];
        float di0 = Dib[d0*NN],   di1 = Dib[d1*NN];
        float dj0 = Djb[d0*NN],   dj1 = Djb[d1*NN];
        float ci0 = Cib[d0*NN],   ci1 = Cib[d1*NN];
        float cj0 = Cjb[d0*NN],   cj1 = Cjb[d1*NN];
        a0.x = (a0.x + di0 + cj0 + g0) * mv;
        a0.y = (a0.y + di1 + cj1 + g1) * mv;
        a1.x = (a1.x + dj0 + ci0 + g0) * mv;
        a1.y = (a1.y + dj1 + ci1 + g1) * mv;
        acc0[q] = f2pack(a0.x, a0.y);
        acc1[q] = f2pack(a1.x, a1.y);
    }

    if (FIN) {
        ulonglong2* op0 = (ulonglong2*)(out_final + s0 * COUT);
        ulonglong2* op1 = (ulonglong2*)(out_final + s1 * COUT);
#pragma unroll
        for (int q = 0; q < COUT/4; q++) {
            op0[q] = make_ulonglong2(acc0[2*q], acc0[2*q+1]);
            op1[q] = make_ulonglong2(acc1[2*q], acc1[2*q+1]);
        }
    } else {
        const int WVF = 2048, WWF = 3072;
#pragma unroll 1
        for (int pass = 0; pass < 2; pass++) {
            const int WF = pass ? WWF : WVF;
            const float* bias = pass ? bw : bv;
            float* outg = pass ? g_w : g_v;
#pragma unroll 1
            for (int half = 0; half < 2; half++) {
                u64t p0[8], p1[8];
                const u64t* b2 = (const u64t*)(bias + half*16);
#pragma unroll
                for (int e = 0; e < 8; e++) { u64t bb2 = b2[e]; p0[e] = bb2; p1[e] = bb2; }
#pragma unroll 1
                for (int dq = 0; dq < COUT/2; dq++) {
                    float2 a0 = f2unpack(acc0[dq]);
                    float2 a1 = f2unpack(acc1[dq]);
                    u64t a0x = f2pack(a0.x, a0.x), a0y = f2pack(a0.y, a0.y);
                    u64t a1x = f2pack(a1.x, a1.x), a1y = f2pack(a1.y, a1.y);
                    const ulonglong2* r0 = (const ulonglong2*)(s + WF + (2*dq+0)*CC + half*16);
                    const ulonglong2* r1 = (const ulonglong2*)(s + WF + (2*dq+1)*CC + half*16);
#pragma unroll
                    for (int q = 0; q < 4; q++) {
                        ulonglong2 w0 = r0[q];
                        ulonglong2 w1 = r1[q];
                        f2fma(p0[2*q+0], a0x, w0.x); f2fma(p0[2*q+1], a0x, w0.y);
                        f2fma(p0[2*q+0], a0y, w1.x); f2fma(p0[2*q+1], a0y, w1.y);
                        f2fma(p1[2*q+0], a1x, w0.x); f2fma(p1[2*q+1], a1x, w0.y);
                        f2fma(p1[2*q+0], a1y, w1.x); f2fma(p1[2*q+1], a1y, w1.y);
                    }
                }
                ulonglong2* o0 = (ulonglong2*)(outg + s0*CC + half*16);
                ulonglong2* o1 = (ulonglong2*)(outg + s1*CC + half*16);
#pragma unroll
                for (int q = 0; q < 4; q++) {
                    o0[q] = make_ulonglong2(p0[2*q], p0[2*q+1]);
                    o1[q] = make_ulonglong2(p1[2*q], p1[2*q+1]);
                }
            }
        }
    }
}

// ---------- localconv: 16x16 tiles, cp.async double-buffered K pipeline ----------
#define LK 12
#define VS_FL (16*LK*32)
#define WS_J_STRIDE 109
#define WS_FL (16*WS_J_STRIDE*4)
#define BUF_FL (VS_FL + WS_FL)
#define WO_OFFL (2*BUF_FL)
#define DS_BYTES ((WO_OFFL + 1024)*4)
#define ZST 34

__global__ __launch_bounds__(256) void k_local(const float* __restrict__ Wo,
                                               const float* __restrict__ bo) {
    extern __shared__ __align__(16) float sm[];
    float* wo = sm + WO_OFFL;
    float* zs = sm;

    int blk = blockIdx.x;
    int q9 = blk % 9;
    int it3 = q9 / 3, jt3 = q9 % 3;
    int m = (blk / 9) % NN, b = blk / (9*NN);
    int i0 = it3 * 16, j0 = jt3 * 16;
    int tid = threadIdx.x;
    uint32_t smbase = smem_u32(sm);

    ((float4*)wo)[tid] = __ldg(((const float4*)Wo) + tid);

    auto load_chunk = [&](int kc, int bi) {
        uint32_t vb = smbase + (bi*BUF_FL)*4;
        uint32_t wb = vb + VS_FL*4;
        for (int idx = tid; idx < 16*LK*8; idx += 256) {
            int r = idx >> 3, c4 = idx & 7;
            int iiL = r / LK, k = r % LK;
            const float* src = g_v + ((((size_t)b*NN + i0+iiL)*NN + kc*LK + k)*NN + m)*CC + c4*4;
            cpa16(vb + ((iiL*LK + k)*8 + c4)*16, src);
        }
        for (int idx = tid; idx < 16*LK*8; idx += 256) {
            int r = idx >> 3, c4 = idx & 7;
            int jjL = r / LK, k = r % LK;
            const float* src = g_w + ((((size_t)b*NN + kc*LK + k)*NN + j0+jjL)*NN + m)*CC + c4*4;
            cpa16(wb + (jjL*WS_J_STRIDE + k*9 + c4)*16, src);
        }
    };

    int ct = tid & 7, jt = (tid >> 3) & 7, it = tid >> 6;
    u64t acc[4][2][2];
#pragma unroll
    for (int r = 0; r < 4; r++)
#pragma unroll
        for (int d = 0; d < 2; d++) { acc[r][d][0] = 0ULL; acc[r][d][1] = 0ULL; }

    load_chunk(0, 0);
    CP_COMMIT();

#pragma unroll 1
    for (int kc = 0; kc < 4; kc++) {
        int bi = kc & 1;
        if (kc + 1 < 4) { load_chunk(kc + 1, (kc + 1) & 1); CP_COMMIT(); }
        if (kc + 1 < 4) { CP_WAIT(1); } else { CP_WAIT(0); }
        __syncthreads();

        const float* vs = sm + bi*BUF_FL;
        const float* ws = vs + VS_FL;
#pragma unroll 4
        for (int k = 0; k < LK; k++) {
            ulonglong2 v[4];
#pragma unroll
            for (int r = 0; r < 4; r++)
                v[r] = *((const ulonglong2*)vs + ((it*4+r)*LK + k)*8 + ct);
            ulonglong2 w[2];
#pragma unroll
            for (int d = 0; d < 2; d++)
                w[d] = *((const ulonglong2*)ws + (jt*2+d)*WS_J_STRIDE + k*9 + ct);
#pragma unroll
            for (int r = 0; r < 4; r++)
#pragma unroll
                for (int d = 0; d < 2; d++) {
                    f2fma(acc[r][d][0], v[r].x, w[d].x);
                    f2fma(acc[r][d][1], v[r].y, w[d].y);
                }
        }
        __syncthreads();
    }

#pragma unroll
    for (int r = 0; r < 4; r++)
#pragma unroll
        for (int d = 0; d < 2; d++) {
            int il = it*4 + r, jl = jt*2 + d;
            u64t* zp = (u64t*)(zs + (il*16 + jl)*ZST + ct*4);
            zp[0] = acc[r][d][0];
            zp[1] = acc[r][d][1];
        }
    __syncthreads();

    int site = tid;
    int il = site >> 4, jl = site & 15;
    int gi = i0 + il, gj = j0 + jl;
    u64t oa[16];
#pragma unroll
    for (int q = 0; q < 16; q++) oa[q] = 0ULL;
#pragma unroll 4
    for (int c = 0; c < 32; c++) {
        float zv = zs[site*ZST + c];
        u64t zv2 = f2pack(zv, zv);
        const ulonglong2* wrow = (const ulonglong2*)(wo + c*32);
#pragma unroll
        for (int q = 0; q < 8; q++) {
            ulonglong2 w = wrow[q];
            f2fma(oa[2*q+0], zv2, w.x);
            f2fma(oa[2*q+1], zv2, w.y);
        }
    }
    float mv = g_nv[b*NN+gi] * g_nv[b*NN+gj] * g_nv[b*NN+m];
    float* op = g_t + ((((size_t)b*NN + gi)*NN + gj)*NN + m)*CC;
#pragma unroll
    for (int q = 0; q < 8; q++) {
        float2 p0 = f2unpack(oa[2*q+0]);
        float2 p1 = f2unpack(oa[2*q+1]);
        float e0 = p0.x * (1.0f/NN) + __ldg(bo + 4*q+0);
        float e1 = p0.y * (1.0f/NN) + __ldg(bo + 4*q+1);
        float e2 = p1.x * (1.0f/NN) + __ldg(bo + 4*q+2);
        float e3 = p1.y * (1.0f/NN) + __ldg(bo + 4*q+3);
        e0 = (e0 > 0.f ? e0 : 0.f) * mv;
        e1 = (e1 > 0.f ? e1 : 0.f) * mv;
        e2 = (e2 > 0.f ? e2 : 0.f) * mv;
        e3 = (e3 > 0.f ? e3 : 0.f) * mv;
        *(float4*)(op + 4*q) = make_float4(e0, e1, e2, e3);
    }
}

// ---------- host ----------
extern "C" void kernel_launch(void* const* d_in, const int* in_sizes, int n_in,
                              void* d_out, int out_size) {
    (void)in_sizes; (void)n_in; (void)out_size;
    const float* x    = (const float*)d_in[0];
    const void*  mask = d_in[1];

    cudaFuncSetAttribute(k_local, cudaFuncAttributeMaxDynamicSharedMemorySize, DS_BYTES);

    k_mask<<<1, 1024>>>(mask);
    k_build_t<<<NSITES/256, 256>>>(x);

    for (int l = 0; l < 2; l++) {
        const float* W  = (const float*)d_in[2 + 8*l];
        const float* bb = (const float*)d_in[3 + 8*l];
        const float* Wv = (const float*)d_in[4 + 8*l];
        const float* bv = (const float*)d_in[5 + 8*l];
        const float* Ww = (const float*)d_in[6 + 8*l];
        const float* bw = (const float*)d_in[7 + 8*l];
        const float* Wo = (const float*)d_in[8 + 8*l];
        const float* bo = (const float*)d_in[9 + 8*l];
        k_sums<32><<<NIMC/256, 256>>>(W, l);
        k_conv<32, false><<<BATCH*BPB, 256>>>(W, bb, Wv, bv, Ww, bw, nullptr, l);
        k_local<<<BATCH*NN*9, 256, DS_BYTES>>>(Wo, bo);
    }

    const float* Wf  = (const float*)d_in[18];
    const float* bf  = (const float*)d_in[19];
    k_sums<16><<<NIMC/256, 256>>>(Wf, 2);
    k_conv<16, true><<<BATCH*BPB, 256>>>(Wf, bf, nullptr, nullptr, nullptr, nullptr, (float*)d_out, 2);
}

// round 15
// speedup vs baseline: 1.2411x; 1.0247x over previous
#include <cuda_runtime.h>
#include <cstdint>

#define NN 48
#define BATCH 4
#define CC 32
#define NSITES (BATCH*NN*NN*NN)
#define TSIZE  ((size_t)NSITES*CC)
#define NIMC   (BATCH*NN*NN*CC)
#define TOTSZ  (BATCH*NN*CC)
#define NPAIR  1176
#define PTH    (NPAIR*NN)
#define BPB    ((PTH + 255)/256)

typedef unsigned long long u64t;

__device__ __forceinline__ u64t f2pack(float lo, float hi) {
    u64t r; asm("mov.b64 %0, {%1, %2};" : "=l"(r) : "f"(lo), "f"(hi)); return r;
}
__device__ __forceinline__ float2 f2unpack(u64t v) {
    float2 r; asm("mov.b64 {%0, %1}, %2;" : "=f"(r.x), "=f"(r.y) : "l"(v)); return r;
}
__device__ __forceinline__ void f2fma(u64t& d, u64t a, u64t b) {
    asm("fma.rn.f32x2 %0, %1, %2, %0;" : "+l"(d) : "l"(a), "l"(b));
}
__device__ __forceinline__ uint32_t smem_u32(const void* p) {
    uint32_t a;
    asm("{ .reg .u64 t; cvta.to.shared.u64 t, %1; cvt.u32.u64 %0, t; }" : "=r"(a) : "l"(p));
    return a;
}
__device__ __forceinline__ void cpa16(uint32_t dst, const void* src) {
    asm volatile("cp.async.cg.shared.global [%0], [%1], 16;" :: "r"(dst), "l"(src) : "memory");
}
#define CP_COMMIT() asm volatile("cp.async.commit_group;" ::: "memory")
#define CP_WAIT(n)  asm volatile("cp.async.wait_group %0;" :: "n"(n) : "memory")

__device__ float g_t[TSIZE];
__device__ float g_v[TSIZE];
__device__ float g_w[TSIZE];
__device__ float g_D [NIMC];      // [b][node][d][m]
__device__ float g_Cc[NIMC];      // [b][node][d][m]
__device__ float g_tot[3*TOTSZ];
__device__ float g_nv[BATCH*NN];
__device__ int   g_cpairs[BATCH*NPAIR];   // per-batch compacted (valid-first) pair list
__device__ int   g_cnt[BATCH];            // valid-pair counts
__device__ int   g_invc[BATCH];           // invalid counters (scratch)

// ---------- mask detect + node_valid + tot zero + compacted pair table ----------
__global__ void k_mask(const void* __restrict__ mask) {
    __shared__ int smode;
    if (threadIdx.x == 0) {
        const unsigned char* mb = (const unsigned char*)mask;
        unsigned char b0 = mb[0], b1 = mb[1];
        int mode;
        if (b0 == 1 && b1 != 0) mode = 0;
        else if (b0 == 1)       mode = 1;
        else                    mode = 2;
        smode = mode;
    }
    if (threadIdx.x < BATCH) { g_cnt[threadIdx.x] = 0; g_invc[threadIdx.x] = 0; }
    __syncthreads();
    int p = threadIdx.x;
    if (p < BATCH*NN) {
        int b = p / NN, i = p % NN;
        size_t idx = (((size_t)b*NN + i)*NN + i)*NN + i;
        int mode = smode;
        float v;
        if (mode == 0)      v = ((const unsigned char*)mask)[idx] ? 1.f : 0.f;
        else if (mode == 1) v = ((const int*)mask)[idx] ? 1.f : 0.f;
        else                v = (((const float*)mask)[idx] != 0.f) ? 1.f : 0.f;
        g_nv[p] = v;
    }
    for (int q = threadIdx.x; q < 3*TOTSZ; q += 1024) g_tot[q] = 0.f;
    __syncthreads();
    // compaction: valid pairs to front (atomic slots), invalid to tail
    for (int q = threadIdx.x; q < BATCH*NPAIR; q += 1024) {
        int b = q / NPAIR, pr = q % NPAIR;
        int i = 0, rem = pr;
        while (rem >= NN - i) { rem -= NN - i; i++; }
        int j = i + rem;
        bool valid = (g_nv[b*NN+i] != 0.f) && (g_nv[b*NN+j] != 0.f);
        int slot;
        if (valid) slot = atomicAdd(&g_cnt[b], 1);
        else       slot = NPAIR - 1 - atomicAdd(&g_invc[b], 1);
        g_cpairs[b*NPAIR + slot] = (i << 8) | j;
    }
}

// ---------- t build (mask fast-path) ----------
__global__ __launch_bounds__(256) void k_build_t(const float* __restrict__ x) {
    int s = blockIdx.x * 256 + threadIdx.x;
    int m = s % NN, j = (s / NN) % NN, i = (s / (NN*NN)) % NN, b = s / (NN*NN*NN);
    float mv = g_nv[b*NN+i] * g_nv[b*NN+j] * g_nv[b*NN+m];
    float4* out = (float4*)(g_t + (size_t)s * CC);
    if (mv == 0.f) {
        float4 z = make_float4(0.f, 0.f, 0.f, 0.f);
#pragma unroll
        for (int q = 0; q < 8; q++) out[q] = z;
        return;
    }
    const float4* xi = (const float4*)(x + (b*NN + i)*CC);
    const float4* xj = (const float4*)(x + (b*NN + j)*CC);
    const float4* xm = (const float4*)(x + (b*NN + m)*CC);
#pragma unroll
    for (int q = 0; q < 8; q++) {
        float4 a = xi[q], c = xj[q], d = xm[q], r;
        r.x = a.x*c.x*d.x; r.y = a.y*c.y*d.y;
        r.z = a.z*c.z*d.z; r.w = a.w*c.w*d.w;
        out[q] = r;
    }
}

// ---------- rows/diag/cols + D/Cc (transposed) + atomic tot; warp-uniform skip ----------
template<int COUT>
__global__ __launch_bounds__(256) void k_sums(const float* __restrict__ W, int layer) {
    __shared__ float sr[8][CC], sd[8][CC], sc[8][CC];
    int p = blockIdx.x * 256 + threadIdx.x;
    int c = p & 31;
    int m = (p >> 5) % NN;
    int a = (p / (32*NN)) % NN;
    int b = p / (32*NN*NN);
    int ls = threadIdx.x >> 5;

    bool valid = (g_nv[b*NN+a] * g_nv[b*NN+m]) != 0.f;
    float rowv = 0.f, diagv = 0.f, colv = 0.f;

    if (valid) {
        const float* pr = g_t + ((((size_t)b*NN + a)*NN + 0)*NN + m)*CC + c;
        float r0=0.f, r1=0.f, r2=0.f, r3=0.f;
#pragma unroll
        for (int j = 0; j < NN; j += 4) {
            r0 += pr[(size_t)(j+0) * (NN*CC)];
            r1 += pr[(size_t)(j+1) * (NN*CC)];
            r2 += pr[(size_t)(j+2) * (NN*CC)];
            r3 += pr[(size_t)(j+3) * (NN*CC)];
        }
        rowv  = (r0+r1+r2+r3) * (1.0f/NN);
        diagv = pr[(size_t)a * (NN*CC)];

        const float* pc = g_t + ((((size_t)b*NN + 0)*NN + a)*NN + m)*CC + c;
        float s0=0.f, s1=0.f, s2=0.f, s3=0.f;
#pragma unroll
        for (int i = 0; i < NN; i += 4) {
            s0 += pc[(size_t)(i+0) * (NN*NN*CC)];
            s1 += pc[(size_t)(i+1) * (NN*NN*CC)];
            s2 += pc[(size_t)(i+2) * (NN*NN*CC)];
            s3 += pc[(size_t)(i+3) * (NN*NN*CC)];
        }
        colv = (s0+s1+s2+s3) * (1.0f/NN);

        atomicAdd(&g_tot[layer*TOTSZ + (b*NN + m)*CC + c], rowv * (1.0f/NN));
    }

    sr[ls][c] = rowv; sd[ls][c] = diagv; sc[ls][c] = colv;
    __syncthreads();

    if (c < COUT) {
        size_t tidx = (((size_t)(b*NN + a))*COUT + c)*NN + m;
        if (valid) {
            float accD = 0.f, accC = 0.f;
#pragma unroll 8
            for (int c2 = 0; c2 < CC; c2++) {
                accD += sd[ls][c2] * __ldg(W + (2*CC + c2)*COUT + c)
                      + sr[ls][c2] * __ldg(W + (3*CC + c2)*COUT + c);
                accC += sc[ls][c2] * __ldg(W + (4*CC + c2)*COUT + c);
            }
            g_D [tidx] = accD;
            g_Cc[tidx] = accC;
        } else {
            g_D [tidx] = 0.f;
            g_Cc[tidx] = 0.f;
        }
    }
}

// ---------- fused snconv: compacted pairs, heavy-first interleaved blocks ----------
template<int COUT, bool FIN>
__global__ __launch_bounds__(256, 2) void k_conv(const float* __restrict__ W,
                                                 const float* __restrict__ bb,
                                                 const float* __restrict__ Wv,
                                                 const float* __restrict__ bv,
                                                 const float* __restrict__ Ww,
                                                 const float* __restrict__ bw,
                                                 float* __restrict__ out_final,
                                                 int layer) {
    constexpr int WFL = FIN ? (2*CC*COUT) : (2*CC*COUT + 2*CC*CC);
    constexpr int GST = COUT + 2;
    __shared__ __align__(16) float s[WFL + NN*GST];
    float4* s4 = (float4*)s;

    // pair-major interleave: heavy (valid) blocks are consecutive at launch front
    int bblk = blockIdx.x % BATCH;
    int pblk = blockIdx.x / BATCH;
    int cnt  = g_cnt[bblk];
    bool blk_heavy = (pblk * 256) / NN < cnt;   // block-uniform

    if (blk_heavy) {
        {
            const float4* W4 = (const float4*)W;
            if (FIN) {
                for (int idx = threadIdx.x; idx < WFL/4; idx += 256)
                    s4[idx] = W4[idx];
            } else {
                const float4* Wv4 = (const float4*)Wv;
                const float4* Ww4 = (const float4*)Ww;
                for (int idx = threadIdx.x; idx < 1024; idx += 256) {
                    float4 val;
                    if (idx < 512)      val = W4[idx];
                    else if (idx < 768) val = Wv4[idx - 512];
                    else                val = Ww4[idx - 768];
                    s4[idx] = val;
                }
            }
        }
        const float* tot = g_tot + layer*TOTSZ + bblk*(NN*CC);
        for (int idx = threadIdx.x; idx < NN*COUT; idx += 256) {
            int mm = idx / COUT, d = idx % COUT;
            float a = __ldg(bb + d);
            const float* tr = tot + mm*CC;
#pragma unroll 8
            for (int c = 0; c < CC; c++)
                a += tr[c] * __ldg(W + (5*CC + c)*COUT + d);
            s[WFL + mm*GST + d] = a;
        }
        __syncthreads();
    }

    int local = pblk * 256 + threadIdx.x;
    if (local >= PTH) return;
    int m  = local % NN;
    int pr = local / NN;
    int pij = g_cpairs[bblk*NPAIR + pr];
    int i = pij >> 8, j = pij & 255;

    size_t s0 = (((size_t)bblk*NN + i)*NN + j)*NN + m;
    size_t s1 = (((size_t)bblk*NN + j)*NN + i)*NN + m;

    float mv = g_nv[bblk*NN+i] * g_nv[bblk*NN+j] * g_nv[bblk*NN+m];

    if (mv == 0.f) {
        if (FIN) {
            ulonglong2 z = make_ulonglong2(0ULL, 0ULL);
            ulonglong2* op0 = (ulonglong2*)(out_final + s0 * COUT);
            ulonglong2* op1 = (ulonglong2*)(out_final + s1 * COUT);
#pragma unroll
            for (int q = 0; q < COUT/4; q++) { op0[q] = z; op1[q] = z; }
        } else {
            const ulonglong2* bv2 = (const ulonglong2*)bv;
            const ulonglong2* bw2 = (const ulonglong2*)bw;
            ulonglong2* v0 = (ulonglong2*)(g_v + s0*CC);
            ulonglong2* v1 = (ulonglong2*)(g_v + s1*CC);
            ulonglong2* w0 = (ulonglong2*)(g_w + s0*CC);
            ulonglong2* w1 = (ulonglong2*)(g_w + s1*CC);
#pragma unroll
            for (int q = 0; q < CC/4; q++) {
                ulonglong2 a = __ldg(bv2 + q);
                ulonglong2 b2 = __ldg(bw2 + q);
                v0[q] = a; v1[q] = a;
                w0[q] = b2; w1[q] = b2;
            }
        }
        return;
    }

    const float* tv0 = g_t + s0 * CC;
    const float* tv1 = g_t + s1 * CC;

    u64t acc0[COUT/2], acc1[COUT/2];
#pragma unroll
    for (int q = 0; q < COUT/2; q++) { acc0[q] = 0ULL; acc1[q] = 0ULL; }

#pragma unroll 1
    for (int c0 = 0; c0 < CC; c0 += 8) {
        float ta[8], tb[8];
        float4 q4;
        q4 = *(const float4*)(tv0 + c0);     ta[0]=q4.x; ta[1]=q4.y; ta[2]=q4.z; ta[3]=q4.w;
        q4 = *(const float4*)(tv0 + c0 + 4); ta[4]=q4.x; ta[5]=q4.y; ta[6]=q4.z; ta[7]=q4.w;
        q4 = *(const float4*)(tv1 + c0);     tb[0]=q4.x; tb[1]=q4.y; tb[2]=q4.z; tb[3]=q4.w;
        q4 = *(const float4*)(tv1 + c0 + 4); tb[4]=q4.x; tb[5]=q4.y; tb[6]=q4.z; tb[7]=q4.w;
#pragma unroll
        for (int cc = 0; cc < 8; cc++) {
            int c = c0 + cc;
            u64t ta2 = f2pack(ta[cc], ta[cc]);
            u64t tb2 = f2pack(tb[cc], tb[cc]);
            const ulonglong2* w0p = (const ulonglong2*)(s + c*COUT);
            const ulonglong2* w1p = (const ulonglong2*)(s + CC*COUT + c*COUT);
#pragma unroll
            for (int q = 0; q < COUT/4; q++) {
                ulonglong2 w0 = w0p[q];
                ulonglong2 w1 = w1p[q];
                f2fma(acc0[2*q+0], ta2, w0.x);
                f2fma(acc0[2*q+1], ta2, w0.y);
                f2fma(acc0[2*q+0], tb2, w1.x);
                f2fma(acc0[2*q+1], tb2, w1.y);
                f2fma(acc1[2*q+0], tb2, w0.x);
                f2fma(acc1[2*q+1], tb2, w0.y);
                f2fma(acc1[2*q+0], ta2, w1.x);
                f2fma(acc1[2*q+1], ta2, w1.y);
            }
        }
    }

    const float* Dib = g_D  + (((size_t)(bblk*NN + i))*COUT)*NN + m;
    const float* Djb = g_D  + (((size_t)(bblk*NN + j))*COUT)*NN + m;
    const float* Cib = g_Cc + (((size_t)(bblk*NN + i))*COUT)*NN + m;
    const float* Cjb = g_Cc + (((size_t)(bblk*NN + j))*COUT)*NN + m;
    const float* Gs  = s + WFL + m*GST;
#pragma unroll
    for (int q = 0; q < COUT/2; q++) {
        int d0 = 2*q, d1 = 2*q+1;
        float2 a0 = f2unpack(acc0[q]);
        float2 a1 = f2unpack(acc1[q]);
        float g0 = Gs[d0],        g1 = Gs[d1];
        float di0 = Dib[d0*NN],   di1 = Dib[d1*NN];
        float dj0 = Djb[d0*NN],   dj1 = Djb[d1*NN];
        float ci0 = Cib[d0*NN],   ci1 = Cib[d1*NN];
        float cj0 = Cjb[d0*NN],   cj1 = Cjb[d1*NN];
        a0.x = (a0.x + di0 + cj0 + g0) * mv;
        a0.y = (a0.y + di1 + cj1 + g1) * mv;
        a1.x = (a1.x + dj0 + ci0 + g0) * mv;
        a1.y = (a1.y + dj1 + ci1 + g1) * mv;
        acc0[q] = f2pack(a0.x, a0.y);
        acc1[q] = f2pack(a1.x, a1.y);
    }

    if (FIN) {
        ulonglong2* op0 = (ulonglong2*)(out_final + s0 * COUT);
        ulonglong2* op1 = (ulonglong2*)(out_final + s1 * COUT);
#pragma unroll
        for (int q = 0; q < COUT/4; q++) {
            op0[q] = make_ulonglong2(acc0[2*q], acc0[2*q+1]);
            op1[q] = make_ulonglong2(acc1[2*q], acc1[2*q+1]);
        }
    } else {
        const int WVF = 2048, WWF = 3072;
#pragma unroll 1
        for (int pass = 0; pass < 2; pass++) {
            const int WF = pass ? WWF : WVF;
            const float* bias = pass ? bw : bv;
            float* outg = pass ? g_w : g_v;
#pragma unroll 1
            for (int half = 0; half < 2; half++) {
                u64t p0[8], p1[8];
                const u64t* b2 = (const u64t*)(bias + half*16);
#pragma unroll
                for (int e = 0; e < 8; e++) { u64t bb2 = b2[e]; p0[e] = bb2; p1[e] = bb2; }
#pragma unroll 1
                for (int dq = 0; dq < COUT/2; dq++) {
                    float2 a0 = f2unpack(acc0[dq]);
                    float2 a1 = f2unpack(acc1[dq]);
                    u64t a0x = f2pack(a0.x, a0.x), a0y = f2pack(a0.y, a0.y);
                    u64t a1x = f2pack(a1.x, a1.x), a1y = f2pack(a1.y, a1.y);
                    const ulonglong2* r0 = (const ulonglong2*)(s + WF + (2*dq+0)*CC + half*16);
                    const ulonglong2* r1 = (const ulonglong2*)(s + WF + (2*dq+1)*CC + half*16);
#pragma unroll
                    for (int q = 0; q < 4; q++) {
                        ulonglong2 w0 = r0[q];
                        ulonglong2 w1 = r1[q];
                        f2fma(p0[2*q+0], a0x, w0.x); f2fma(p0[2*q+1], a0x, w0.y);
                        f2fma(p0[2*q+0], a0y, w1.x); f2fma(p0[2*q+1], a0y, w1.y);
                        f2fma(p1[2*q+0], a1x, w0.x); f2fma(p1[2*q+1], a1x, w0.y);
                        f2fma(p1[2*q+0], a1y, w1.x); f2fma(p1[2*q+1], a1y, w1.y);
                    }
                }
                ulonglong2* o0 = (ulonglong2*)(outg + s0*CC + half*16);
                ulonglong2* o1 = (ulonglong2*)(outg + s1*CC + half*16);
#pragma unroll
                for (int q = 0; q < 4; q++) {
                    o0[q] = make_ulonglong2(p0[2*q], p0[2*q+1]);
                    o1[q] = make_ulonglong2(p1[2*q], p1[2*q+1]);
                }
            }
        }
    }
}

// ---------- localconv: 16x16 tiles, cp.async double-buffered K pipeline ----------
#define LK 12
#define VS_FL (16*LK*32)
#define WS_J_STRIDE 109
#define WS_FL (16*WS_J_STRIDE*4)
#define BUF_FL (VS_FL + WS_FL)
#define WO_OFFL (2*BUF_FL)
#define DS_BYTES ((WO_OFFL + 1024)*4)
#define ZST 34

__global__ __launch_bounds__(256) void k_local(const float* __restrict__ Wo,
                                               const float* __restrict__ bo) {
    extern __shared__ __align__(16) float sm[];
    float* wo = sm + WO_OFFL;
    float* zs = sm;

    int blk = blockIdx.x;
    int q9 = blk % 9;
    int it3 = q9 / 3, jt3 = q9 % 3;
    int m = (blk / 9) % NN, b = blk / (9*NN);
    int i0 = it3 * 16, j0 = jt3 * 16;
    int tid = threadIdx.x;
    uint32_t smbase = smem_u32(sm);

    ((float4*)wo)[tid] = __ldg(((const float4*)Wo) + tid);

    auto load_chunk = [&](int kc, int bi) {
        uint32_t vb = smbase + (bi*BUF_FL)*4;
        uint32_t wb = vb + VS_FL*4;
        for (int idx = tid; idx < 16*LK*8; idx += 256) {
            int r = idx >> 3, c4 = idx & 7;
            int iiL = r / LK, k = r % LK;
            const float* src = g_v + ((((size_t)b*NN + i0+iiL)*NN + kc*LK + k)*NN + m)*CC + c4*4;
            cpa16(vb + ((iiL*LK + k)*8 + c4)*16, src);
        }
        for (int idx = tid; idx < 16*LK*8; idx += 256) {
            int r = idx >> 3, c4 = idx & 7;
            int jjL = r / LK, k = r % LK;
            const float* src = g_w + ((((size_t)b*NN + kc*LK + k)*NN + j0+jjL)*NN + m)*CC + c4*4;
            cpa16(wb + (jjL*WS_J_STRIDE + k*9 + c4)*16, src);
        }
    };

    int ct = tid & 7, jt = (tid >> 3) & 7, it = tid >> 6;
    u64t acc[4][2][2];
#pragma unroll
    for (int r = 0; r < 4; r++)
#pragma unroll
        for (int d = 0; d < 2; d++) { acc[r][d][0] = 0ULL; acc[r][d][1] = 0ULL; }

    load_chunk(0, 0);
    CP_COMMIT();

#pragma unroll 1
    for (int kc = 0; kc < 4; kc++) {
        int bi = kc & 1;
        if (kc + 1 < 4) { load_chunk(kc + 1, (kc + 1) & 1); CP_COMMIT(); }
        if (kc + 1 < 4) { CP_WAIT(1); } else { CP_WAIT(0); }
        __syncthreads();

        const float* vs = sm + bi*BUF_FL;
        const float* ws = vs + VS_FL;
#pragma unroll 4
        for (int k = 0; k < LK; k++) {
            ulonglong2 v[4];
#pragma unroll
            for (int r = 0; r < 4; r++)
                v[r] = *((const ulonglong2*)vs + ((it*4+r)*LK + k)*8 + ct);
            ulonglong2 w[2];
#pragma unroll
            for (int d = 0; d < 2; d++)
                w[d] = *((const ulonglong2*)ws + (jt*2+d)*WS_J_STRIDE + k*9 + ct);
#pragma unroll
            for (int r = 0; r < 4; r++)
#pragma unroll
                for (int d = 0; d < 2; d++) {
                    f2fma(acc[r][d][0], v[r].x, w[d].x);
                    f2fma(acc[r][d][1], v[r].y, w[d].y);
                }
        }
        __syncthreads();
    }

#pragma unroll
    for (int r = 0; r < 4; r++)
#pragma unroll
        for (int d = 0; d < 2; d++) {
            int il = it*4 + r, jl = jt*2 + d;
            u64t* zp = (u64t*)(zs + (il*16 + jl)*ZST + ct*4);
            zp[0] = acc[r][d][0];
            zp[1] = acc[r][d][1];
        }
    __syncthreads();

    int site = tid;
    int il = site >> 4, jl = site & 15;
    int gi = i0 + il, gj = j0 + jl;
    u64t oa[16];
#pragma unroll
    for (int q = 0; q < 16; q++) oa[q] = 0ULL;
#pragma unroll 4
    for (int c = 0; c < 32; c++) {
        float zv = zs[site*ZST + c];
        u64t zv2 = f2pack(zv, zv);
        const ulonglong2* wrow = (const ulonglong2*)(wo + c*32);
#pragma unroll
        for (int q = 0; q < 8; q++) {
            ulonglong2 w = wrow[q];
            f2fma(oa[2*q+0], zv2, w.x);
            f2fma(oa[2*q+1], zv2, w.y);
        }
    }
    float mv = g_nv[b*NN+gi] * g_nv[b*NN+gj] * g_nv[b*NN+m];
    float* op = g_t + ((((size_t)b*NN + gi)*NN + gj)*NN + m)*CC;
#pragma unroll
    for (int q = 0; q < 8; q++) {
        float2 p0 = f2unpack(oa[2*q+0]);
        float2 p1 = f2unpack(oa[2*q+1]);
        float e0 = p0.x * (1.0f/NN) + __ldg(bo + 4*q+0);
        float e1 = p0.y * (1.0f/NN) + __ldg(bo + 4*q+1);
        float e2 = p1.x * (1.0f/NN) + __ldg(bo + 4*q+2);
        float e3 = p1.y * (1.0f/NN) + __ldg(bo + 4*q+3);
        e0 = (e0 > 0.f ? e0 : 0.f) * mv;
        e1 = (e1 > 0.f ? e1 : 0.f) * mv;
        e2 = (e2 > 0.f ? e2 : 0.f) * mv;
        e3 = (e3 > 0.f ? e3 : 0.f) * mv;
        *(float4*)(op + 4*q) = make_float4(e0, e1, e2, e3);
    }
}

// ---------- host ----------
extern "C" void kernel_launch(void* const* d_in, const int* in_sizes, int n_in,
                              void* d_out, int out_size) {
    (void)in_sizes; (void)n_in; (void)out_size;
    const float* x    = (const float*)d_in[0];
    const void*  mask = d_in[1];

    cudaFuncSetAttribute(k_local, cudaFuncAttributeMaxDynamicSharedMemorySize, DS_BYTES);

    k_mask<<<1, 1024>>>(mask);
    k_build_t<<<NSITES/256, 256>>>(x);

    for (int l = 0; l < 2; l++) {
        const float* W  = (const float*)d_in[2 + 8*l];
        const float* bb = (const float*)d_in[3 + 8*l];
        const float* Wv = (const float*)d_in[4 + 8*l];
        const float* bv = (const float*)d_in[5 + 8*l];
        const float* Ww = (const float*)d_in[6 + 8*l];
        const float* bw = (const float*)d_in[7 + 8*l];
        const float* Wo = (const float*)d_in[8 + 8*l];
        const float* bo = (const float*)d_in[9 + 8*l];
        k_sums<32><<<NIMC/256, 256>>>(W, l);
        k_conv<32, false><<<BATCH*BPB, 256>>>(W, bb, Wv, bv, Ww, bw, nullptr, l);
        k_local<<<BATCH*NN*9, 256, DS_BYTES>>>(Wo, bo);
    }

    const float* Wf  = (const float*)d_in[18];
    const float* bf  = (const float*)d_in[19];
    k_sums<16><<<NIMC/256, 256>>>(Wf, 2);
    k_conv<16, true><<<BATCH*BPB, 256>>>(Wf, bf, nullptr, nullptr, nullptr, nullptr, (float*)d_out, 2);
}

// round 16
// speedup vs baseline: 1.2785x; 1.0302x over previous
#include <cuda_runtime.h>
#include <cstdint>

#define NN 48
#define BATCH 4
#define CC 32
#define NSITES (BATCH*NN*NN*NN)
#define TSIZE  ((size_t)NSITES*CC)
#define NIMC   (BATCH*NN*NN*CC)
#define TOTSZ  (BATCH*NN*CC)
#define NPAIR  1176
#define PTH    (NPAIR*NN)
#define BPB    ((PTH + 255)/256)

typedef unsigned long long u64t;

__device__ __forceinline__ u64t f2pack(float lo, float hi) {
    u64t r; asm("mov.b64 %0, {%1, %2};" : "=l"(r) : "f"(lo), "f"(hi)); return r;
}
__device__ __forceinline__ float2 f2unpack(u64t v) {
    float2 r; asm("mov.b64 {%0, %1}, %2;" : "=f"(r.x), "=f"(r.y) : "l"(v)); return r;
}
__device__ __forceinline__ void f2fma(u64t& d, u64t a, u64t b) {
    asm("fma.rn.f32x2 %0, %1, %2, %0;" : "+l"(d) : "l"(a), "l"(b));
}
__device__ __forceinline__ uint32_t smem_u32(const void* p) {
    uint32_t a;
    asm("{ .reg .u64 t; cvta.to.shared.u64 t, %1; cvt.u32.u64 %0, t; }" : "=r"(a) : "l"(p));
    return a;
}
__device__ __forceinline__ void cpa16(uint32_t dst, const void* src) {
    asm volatile("cp.async.cg.shared.global [%0], [%1], 16;" :: "r"(dst), "l"(src) : "memory");
}
#define CP_COMMIT() asm volatile("cp.async.commit_group;" ::: "memory")
#define CP_WAIT(n)  asm volatile("cp.async.wait_group %0;" :: "n"(n) : "memory")

__device__ float g_t[TSIZE];
__device__ float g_v[TSIZE];
__device__ float g_w[TSIZE];
__device__ float g_D [NIMC];      // [b][node][d][m]
__device__ float g_Cc[NIMC];      // [b][node][d][m]
__device__ float g_G [BATCH*NN*CC];
__device__ float g_tot[3*TOTSZ];
__device__ float g_nv[BATCH*NN];
__device__ int   g_cpairs[BATCH*NPAIR];
__device__ int   g_cnt[BATCH];
__device__ int   g_invc[BATCH];

// ---------- mask detect + node_valid + tot zero + compacted pair table ----------
__global__ void k_mask(const void* __restrict__ mask) {
    __shared__ int smode;
    if (threadIdx.x == 0) {
        const unsigned char* mb = (const unsigned char*)mask;
        unsigned char b0 = mb[0], b1 = mb[1];
        int mode;
        if (b0 == 1 && b1 != 0) mode = 0;
        else if (b0 == 1)       mode = 1;
        else                    mode = 2;
        smode = mode;
    }
    if (threadIdx.x < BATCH) { g_cnt[threadIdx.x] = 0; g_invc[threadIdx.x] = 0; }
    __syncthreads();
    int p = threadIdx.x;
    if (p < BATCH*NN) {
        int b = p / NN, i = p % NN;
        size_t idx = (((size_t)b*NN + i)*NN + i)*NN + i;
        int mode = smode;
        float v;
        if (mode == 0)      v = ((const unsigned char*)mask)[idx] ? 1.f : 0.f;
        else if (mode == 1) v = ((const int*)mask)[idx] ? 1.f : 0.f;
        else                v = (((const float*)mask)[idx] != 0.f) ? 1.f : 0.f;
        g_nv[p] = v;
    }
    for (int q = threadIdx.x; q < 3*TOTSZ; q += 1024) g_tot[q] = 0.f;
    __syncthreads();
    for (int q = threadIdx.x; q < BATCH*NPAIR; q += 1024) {
        int b = q / NPAIR, pr = q % NPAIR;
        int i = 0, rem = pr;
        while (rem >= NN - i) { rem -= NN - i; i++; }
        int j = i + rem;
        bool valid = (g_nv[b*NN+i] != 0.f) && (g_nv[b*NN+j] != 0.f);
        int slot;
        if (valid) slot = atomicAdd(&g_cnt[b], 1);
        else       slot = NPAIR - 1 - atomicAdd(&g_invc[b], 1);
        g_cpairs[b*NPAIR + slot] = (i << 8) | j;
    }
}

// ---------- t build (mask fast-path) ----------
__global__ __launch_bounds__(256) void k_build_t(const float* __restrict__ x) {
    int s = blockIdx.x * 256 + threadIdx.x;
    int m = s % NN, j = (s / NN) % NN, i = (s / (NN*NN)) % NN, b = s / (NN*NN*NN);
    float mv = g_nv[b*NN+i] * g_nv[b*NN+j] * g_nv[b*NN+m];
    float4* out = (float4*)(g_t + (size_t)s * CC);
    if (mv == 0.f) {
        float4 z = make_float4(0.f, 0.f, 0.f, 0.f);
#pragma unroll
        for (int q = 0; q < 8; q++) out[q] = z;
        return;
    }
    const float4* xi = (const float4*)(x + (b*NN + i)*CC);
    const float4* xj = (const float4*)(x + (b*NN + j)*CC);
    const float4* xm = (const float4*)(x + (b*NN + m)*CC);
#pragma unroll
    for (int q = 0; q < 8; q++) {
        float4 a = xi[q], c = xj[q], d = xm[q], r;
        r.x = a.x*c.x*d.x; r.y = a.y*c.y*d.y;
        r.z = a.z*c.z*d.z; r.w = a.w*c.w*d.w;
        out[q] = r;
    }
}

// ---------- rows/diag/cols + D/Cc (transposed) + atomic tot; warp-uniform skip ----------
template<int COUT>
__global__ __launch_bounds__(256) void k_sums(const float* __restrict__ W, int layer) {
    __shared__ float sr[8][CC], sd[8][CC], sc[8][CC];
    int p = blockIdx.x * 256 + threadIdx.x;
    int c = p & 31;
    int m = (p >> 5) % NN;
    int a = (p / (32*NN)) % NN;
    int b = p / (32*NN*NN);
    int ls = threadIdx.x >> 5;

    bool valid = (g_nv[b*NN+a] * g_nv[b*NN+m]) != 0.f;
    float rowv = 0.f, diagv = 0.f, colv = 0.f;

    if (valid) {
        const float* pr = g_t + ((((size_t)b*NN + a)*NN + 0)*NN + m)*CC + c;
        float r0=0.f, r1=0.f, r2=0.f, r3=0.f;
#pragma unroll
        for (int j = 0; j < NN; j += 4) {
            r0 += pr[(size_t)(j+0) * (NN*CC)];
            r1 += pr[(size_t)(j+1) * (NN*CC)];
            r2 += pr[(size_t)(j+2) * (NN*CC)];
            r3 += pr[(size_t)(j+3) * (NN*CC)];
        }
        rowv  = (r0+r1+r2+r3) * (1.0f/NN);
        diagv = pr[(size_t)a * (NN*CC)];

        const float* pc = g_t + ((((size_t)b*NN + 0)*NN + a)*NN + m)*CC + c;
        float s0=0.f, s1=0.f, s2=0.f, s3=0.f;
#pragma unroll
        for (int i = 0; i < NN; i += 4) {
            s0 += pc[(size_t)(i+0) * (NN*NN*CC)];
            s1 += pc[(size_t)(i+1) * (NN*NN*CC)];
            s2 += pc[(size_t)(i+2) * (NN*NN*CC)];
            s3 += pc[(size_t)(i+3) * (NN*NN*CC)];
        }
        colv = (s0+s1+s2+s3) * (1.0f/NN);

        atomicAdd(&g_tot[layer*TOTSZ + (b*NN + m)*CC + c], rowv * (1.0f/NN));
    }

    sr[ls][c] = rowv; sd[ls][c] = diagv; sc[ls][c] = colv;
    __syncthreads();

    if (c < COUT) {
        size_t tidx = (((size_t)(b*NN + a))*COUT + c)*NN + m;
        if (valid) {
            float accD = 0.f, accC = 0.f;
#pragma unroll 8
            for (int c2 = 0; c2 < CC; c2++) {
                accD += sd[ls][c2] * __ldg(W + (2*CC + c2)*COUT + c)
                      + sr[ls][c2] * __ldg(W + (3*CC + c2)*COUT + c);
                accC += sc[ls][c2] * __ldg(W + (4*CC + c2)*COUT + c);
            }
            g_D [tidx] = accD;
            g_Cc[tidx] = accC;
        } else {
            g_D [tidx] = 0.f;
            g_Cc[tidx] = 0.f;
        }
    }
}

// ---------- G table, computed ONCE per conv: G[b,m,d] = bb[d] + tot·W5 ----------
template<int COUT>
__global__ __launch_bounds__(256) void k_g(const float* __restrict__ W,
                                           const float* __restrict__ bb, int layer) {
    int q = blockIdx.x * 256 + threadIdx.x;
    if (q >= BATCH*NN*COUT) return;
    int d = q % COUT;
    int mm = (q / COUT) % NN;
    int b = q / (COUT*NN);
    const float* tr = g_tot + layer*TOTSZ + (b*NN + mm)*CC;
    float a = __ldg(bb + d);
#pragma unroll 8
    for (int c = 0; c < CC; c++)
        a += tr[c] * __ldg(W + (5*CC + c)*COUT + d);
    g_G[(b*NN + mm)*CC + d] = a;
}

// ---------- fused snconv: compacted pairs; G staged from precompute ----------
template<int COUT, bool FIN>
__global__ __launch_bounds__(256, 2) void k_conv(const float* __restrict__ W,
                                                 const float* __restrict__ Wv,
                                                 const float* __restrict__ bv,
                                                 const float* __restrict__ Ww,
                                                 const float* __restrict__ bw,
                                                 float* __restrict__ out_final) {
    constexpr int WFL = FIN ? (2*CC*COUT) : (2*CC*COUT + 2*CC*CC);
    constexpr int GST = COUT + 2;
    __shared__ __align__(16) float s[WFL + NN*GST];
    float4* s4 = (float4*)s;

    int bblk = blockIdx.x % BATCH;
    int pblk = blockIdx.x / BATCH;
    int cnt  = g_cnt[bblk];
    bool blk_heavy = (pblk * 256) / NN < cnt;

    if (blk_heavy) {
        {
            const float4* W4 = (const float4*)W;
            if (FIN) {
                for (int idx = threadIdx.x; idx < WFL/4; idx += 256)
                    s4[idx] = W4[idx];
            } else {
                const float4* Wv4 = (const float4*)Wv;
                const float4* Ww4 = (const float4*)Ww;
                for (int idx = threadIdx.x; idx < 1024; idx += 256) {
                    float4 val;
                    if (idx < 512)      val = W4[idx];
                    else if (idx < 768) val = Wv4[idx - 512];
                    else                val = Ww4[idx - 768];
                    s4[idx] = val;
                }
            }
        }
        // stage precomputed G (coalesced gmem read -> padded smem)
        for (int idx = threadIdx.x; idx < NN*COUT; idx += 256) {
            int mm = idx / COUT, d = idx % COUT;
            s[WFL + mm*GST + d] = g_G[(bblk*NN + mm)*CC + d];
        }
        __syncthreads();
    }

    int local = pblk * 256 + threadIdx.x;
    if (local >= PTH) return;
    int m  = local % NN;
    int pr = local / NN;
    int pij = g_cpairs[bblk*NPAIR + pr];
    int i = pij >> 8, j = pij & 255;

    size_t s0 = (((size_t)bblk*NN + i)*NN + j)*NN + m;
    size_t s1 = (((size_t)bblk*NN + j)*NN + i)*NN + m;

    float mv = g_nv[bblk*NN+i] * g_nv[bblk*NN+j] * g_nv[bblk*NN+m];

    if (mv == 0.f) {
        if (FIN) {
            ulonglong2 z = make_ulonglong2(0ULL, 0ULL);
            ulonglong2* op0 = (ulonglong2*)(out_final + s0 * COUT);
            ulonglong2* op1 = (ulonglong2*)(out_final + s1 * COUT);
#pragma unroll
            for (int q = 0; q < COUT/4; q++) { op0[q] = z; op1[q] = z; }
        } else {
            const ulonglong2* bv2 = (const ulonglong2*)bv;
            const ulonglong2* bw2 = (const ulonglong2*)bw;
            ulonglong2* v0 = (ulonglong2*)(g_v + s0*CC);
            ulonglong2* v1 = (ulonglong2*)(g_v + s1*CC);
            ulonglong2* w0 = (ulonglong2*)(g_w + s0*CC);
            ulonglong2* w1 = (ulonglong2*)(g_w + s1*CC);
#pragma unroll
            for (int q = 0; q < CC/4; q++) {
                ulonglong2 a = __ldg(bv2 + q);
                ulonglong2 b2 = __ldg(bw2 + q);
                v0[q] = a; v1[q] = a;
                w0[q] = b2; w1[q] = b2;
            }
        }
        return;
    }

    const float* tv0 = g_t + s0 * CC;
    const float* tv1 = g_t + s1 * CC;

    u64t acc0[COUT/2], acc1[COUT/2];
#pragma unroll
    for (int q = 0; q < COUT/2; q++) { acc0[q] = 0ULL; acc1[q] = 0ULL; }

#pragma unroll 1
    for (int c0 = 0; c0 < CC; c0 += 8) {
        float ta[8], tb[8];
        float4 q4;
        q4 = *(const float4*)(tv0 + c0);     ta[0]=q4.x; ta[1]=q4.y; ta[2]=q4.z; ta[3]=q4.w;
        q4 = *(const float4*)(tv0 + c0 + 4); ta[4]=q4.x; ta[5]=q4.y; ta[6]=q4.z; ta[7]=q4.w;
        q4 = *(const float4*)(tv1 + c0);     tb[0]=q4.x; tb[1]=q4.y; tb[2]=q4.z; tb[3]=q4.w;
        q4 = *(const float4*)(tv1 + c0 + 4); tb[4]=q4.x; tb[5]=q4.y; tb[6]=q4.z; tb[7]=q4.w;
#pragma unroll
        for (int cc = 0; cc < 8; cc++) {
            int c = c0 + cc;
            u64t ta2 = f2pack(ta[cc], ta[cc]);
            u64t tb2 = f2pack(tb[cc], tb[cc]);
            const ulonglong2* w0p = (const ulonglong2*)(s + c*COUT);
            const ulonglong2* w1p = (const ulonglong2*)(s + CC*COUT + c*COUT);
#pragma unroll
            for (int q = 0; q < COUT/4; q++) {
                ulonglong2 w0 = w0p[q];
                ulonglong2 w1 = w1p[q];
                f2fma(acc0[2*q+0], ta2, w0.x);
                f2fma(acc0[2*q+1], ta2, w0.y);
                f2fma(acc0[2*q+0], tb2, w1.x);
                f2fma(acc0[2*q+1], tb2, w1.y);
                f2fma(acc1[2*q+0], tb2, w0.x);
                f2fma(acc1[2*q+1], tb2, w0.y);
                f2fma(acc1[2*q+0], ta2, w1.x);
                f2fma(acc1[2*q+1], ta2, w1.y);
            }
        }
    }

    const float* Dib = g_D  + (((size_t)(bblk*NN + i))*COUT)*NN + m;
    const float* Djb = g_D  + (((size_t)(bblk*NN + j))*COUT)*NN + m;
    const float* Cib = g_Cc + (((size_t)(bblk*NN + i))*COUT)*NN + m;
    const float* Cjb = g_Cc + (((size_t)(bblk*NN + j))*COUT)*NN + m;
    const float* Gs  = s + WFL + m*GST;
#pragma unroll
    for (int q = 0; q < COUT/2; q++) {
        int d0 = 2*q, d1 = 2*q+1;
        float2 a0 = f2unpack(acc0[q]);
        float2 a1 = f2unpack(acc1[q]);
        float g0 = Gs[d0],        g1 = Gs[d1];
        float di0 = Dib[d0*NN],   di1 = Dib[d1*NN];
        float dj0 = Djb[d0*NN],   dj1 = Djb[d1*NN];
        float ci0 = Cib[d0*NN],   ci1 = Cib[d1*NN];
        float cj0 = Cjb[d0*NN],   cj1 = Cjb[d1*NN];
        a0.x = (a0.x + di0 + cj0 + g0) * mv;
        a0.y = (a0.y + di1 + cj1 + g1) * mv;
        a1.x = (a1.x + dj0 + ci0 + g0) * mv;
        a1.y = (a1.y + dj1 + ci1 + g1) * mv;
        acc0[q] = f2pack(a0.x, a0.y);
        acc1[q] = f2pack(a1.x, a1.y);
    }

    if (FIN) {
        ulonglong2* op0 = (ulonglong2*)(out_final + s0 * COUT);
        ulonglong2* op1 = (ulonglong2*)(out_final + s1 * COUT);
#pragma unroll
        for (int q = 0; q < COUT/4; q++) {
            op0[q] = make_ulonglong2(acc0[2*q], acc0[2*q+1]);
            op1[q] = make_ulonglong2(acc1[2*q], acc1[2*q+1]);
        }
    } else {
        const int WVF = 2048, WWF = 3072;
#pragma unroll 1
        for (int pass = 0; pass < 2; pass++) {
            const int WF = pass ? WWF : WVF;
            const float* bias = pass ? bw : bv;
            float* outg = pass ? g_w : g_v;
#pragma unroll 1
            for (int half = 0; half < 2; half++) {
                u64t p0[8], p1[8];
                const u64t* b2 = (const u64t*)(bias + half*16);
#pragma unroll
                for (int e = 0; e < 8; e++) { u64t bb2 = b2[e]; p0[e] = bb2; p1[e] = bb2; }
#pragma unroll 1
                for (int dq = 0; dq < COUT/2; dq++) {
                    float2 a0 = f2unpack(acc0[dq]);
                    float2 a1 = f2unpack(acc1[dq]);
                    u64t a0x = f2pack(a0.x, a0.x), a0y = f2pack(a0.y, a0.y);
                    u64t a1x = f2pack(a1.x, a1.x), a1y = f2pack(a1.y, a1.y);
                    const ulonglong2* r0 = (const ulonglong2*)(s + WF + (2*dq+0)*CC + half*16);
                    const ulonglong2* r1 = (const ulonglong2*)(s + WF + (2*dq+1)*CC + half*16);
#pragma unroll
                    for (int q = 0; q < 4; q++) {
                        ulonglong2 w0 = r0[q];
                        ulonglong2 w1 = r1[q];
                        f2fma(p0[2*q+0], a0x, w0.x); f2fma(p0[2*q+1], a0x, w0.y);
                        f2fma(p0[2*q+0], a0y, w1.x); f2fma(p0[2*q+1], a0y, w1.y);
                        f2fma(p1[2*q+0], a1x, w0.x); f2fma(p1[2*q+1], a1x, w0.y);
                        f2fma(p1[2*q+0], a1y, w1.x); f2fma(p1[2*q+1], a1y, w1.y);
                    }
                }
                ulonglong2* o0 = (ulonglong2*)(outg + s0*CC + half*16);
                ulonglong2* o1 = (ulonglong2*)(outg + s1*CC + half*16);
#pragma unroll
                for (int q = 0; q < 4; q++) {
                    o0[q] = make_ulonglong2(p0[2*q], p0[2*q+1]);
                    o1[q] = make_ulonglong2(p1[2*q], p1[2*q+1]);
                }
            }
        }
    }
}

// ---------- localconv: 16x16 tiles, cp.async double-buffered K pipeline ----------
#define LK 12
#define VS_FL (16*LK*32)
#define WS_J_STRIDE 109
#define WS_FL (16*WS_J_STRIDE*4)
#define BUF_FL (VS_FL + WS_FL)
#define WO_OFFL (2*BUF_FL)
#define DS_BYTES ((WO_OFFL + 1024)*4)
#define ZST 34

__global__ __launch_bounds__(256) void k_local(const float* __restrict__ Wo,
                                               const float* __restrict__ bo) {
    extern __shared__ __align__(16) float sm[];
    float* wo = sm + WO_OFFL;
    float* zs = sm;

    int blk = blockIdx.x;
    int q9 = blk % 9;
    int it3 = q9 / 3, jt3 = q9 % 3;
    int m = (blk / 9) % NN, b = blk / (9*NN);
    int i0 = it3 * 16, j0 = jt3 * 16;
    int tid = threadIdx.x;
    uint32_t smbase = smem_u32(sm);

    ((float4*)wo)[tid] = __ldg(((const float4*)Wo) + tid);

    auto load_chunk = [&](int kc, int bi) {
        uint32_t vb = smbase + (bi*BUF_FL)*4;
        uint32_t wb = vb + VS_FL*4;
        for (int idx = tid; idx < 16*LK*8; idx += 256) {
            int r = idx >> 3, c4 = idx & 7;
            int iiL = r / LK, k = r % LK;
            const float* src = g_v + ((((size_t)b*NN + i0+iiL)*NN + kc*LK + k)*NN + m)*CC + c4*4;
            cpa16(vb + ((iiL*LK + k)*8 + c4)*16, src);
        }
        for (int idx = tid; idx < 16*LK*8; idx += 256) {
            int r = idx >> 3, c4 = idx & 7;
            int jjL = r / LK, k = r % LK;
            const float* src = g_w + ((((size_t)b*NN + kc*LK + k)*NN + j0+jjL)*NN + m)*CC + c4*4;
            cpa16(wb + (jjL*WS_J_STRIDE + k*9 + c4)*16, src);
        }
    };

    int ct = tid & 7, jt = (tid >> 3) & 7, it = tid >> 6;
    u64t acc[4][2][2];
#pragma unroll
    for (int r = 0; r < 4; r++)
#pragma unroll
        for (int d = 0; d < 2; d++) { acc[r][d][0] = 0ULL; acc[r][d][1] = 0ULL; }

    load_chunk(0, 0);
    CP_COMMIT();

#pragma unroll 1
    for (int kc = 0; kc < 4; kc++) {
        int bi = kc & 1;
        if (kc + 1 < 4) { load_chunk(kc + 1, (kc + 1) & 1); CP_COMMIT(); }
        if (kc + 1 < 4) { CP_WAIT(1); } else { CP_WAIT(0); }
        __syncthreads();

        const float* vs = sm + bi*BUF_FL;
        const float* ws = vs + VS_FL;
#pragma unroll 4
        for (int k = 0; k < LK; k++) {
            ulonglong2 v[4];
#pragma unroll
            for (int r = 0; r < 4; r++)
                v[r] = *((const ulonglong2*)vs + ((it*4+r)*LK + k)*8 + ct);
            ulonglong2 w[2];
#pragma unroll
            for (int d = 0; d < 2; d++)
                w[d] = *((const ulonglong2*)ws + (jt*2+d)*WS_J_STRIDE + k*9 + ct);
#pragma unroll
            for (int r = 0; r < 4; r++)
#pragma unroll
                for (int d = 0; d < 2; d++) {
                    f2fma(acc[r][d][0], v[r].x, w[d].x);
                    f2fma(acc[r][d][1], v[r].y, w[d].y);
                }
        }
        __syncthreads();
    }

#pragma unroll
    for (int r = 0; r < 4; r++)
#pragma unroll
        for (int d = 0; d < 2; d++) {
            int il = it*4 + r, jl = jt*2 + d;
            u64t* zp = (u64t*)(zs + (il*16 + jl)*ZST + ct*4);
            zp[0] = acc[r][d][0];
            zp[1] = acc[r][d][1];
        }
    __syncthreads();

    int site = tid;
    int il = site >> 4, jl = site & 15;
    int gi = i0 + il, gj = j0 + jl;
    u64t oa[16];
#pragma unroll
    for (int q = 0; q < 16; q++) oa[q] = 0ULL;
#pragma unroll 4
    for (int c = 0; c < 32; c++) {
        float zv = zs[site*ZST + c];
        u64t zv2 = f2pack(zv, zv);
        const ulonglong2* wrow = (const ulonglong2*)(wo + c*32);
#pragma unroll
        for (int q = 0; q < 8; q++) {
            ulonglong2 w = wrow[q];
            f2fma(oa[2*q+0], zv2, w.x);
            f2fma(oa[2*q+1], zv2, w.y);
        }
    }
    float mv = g_nv[b*NN+gi] * g_nv[b*NN+gj] * g_nv[b*NN+m];
    float* op = g_t + ((((size_t)b*NN + gi)*NN + gj)*NN + m)*CC;
#pragma unroll
    for (int q = 0; q < 8; q++) {
        float2 p0 = f2unpack(oa[2*q+0]);
        float2 p1 = f2unpack(oa[2*q+1]);
        float e0 = p0.x * (1.0f/NN) + __ldg(bo + 4*q+0);
        float e1 = p0.y * (1.0f/NN) + __ldg(bo + 4*q+1);
        float e2 = p1.x * (1.0f/NN) + __ldg(bo + 4*q+2);
        float e3 = p1.y * (1.0f/NN) + __ldg(bo + 4*q+3);
        e0 = (e0 > 0.f ? e0 : 0.f) * mv;
        e1 = (e1 > 0.f ? e1 : 0.f) * mv;
        e2 = (e2 > 0.f ? e2 : 0.f) * mv;
        e3 = (e3 > 0.f ? e3 : 0.f) * mv;
        *(float4*)(op + 4*q) = make_float4(e0, e1, e2, e3);
    }
}

// ---------- host ----------
extern "C" void kernel_launch(void* const* d_in, const int* in_sizes, int n_in,
                              void* d_out, int out_size) {
    (void)in_sizes; (void)n_in; (void)out_size;
    const float* x    = (const float*)d_in[0];
    const void*  mask = d_in[1];

    cudaFuncSetAttribute(k_local, cudaFuncAttributeMaxDynamicSharedMemorySize, DS_BYTES);

    k_mask<<<1, 1024>>>(mask);
    k_build_t<<<NSITES/256, 256>>>(x);

    for (int l = 0; l < 2; l++) {
        const float* W  = (const float*)d_in[2 + 8*l];
        const float* bb = (const float*)d_in[3 + 8*l];
        const float* Wv = (const float*)d_in[4 + 8*l];
        const float* bv = (const float*)d_in[5 + 8*l];
        const float* Ww = (const float*)d_in[6 + 8*l];
        const float* bw = (const float*)d_in[7 + 8*l];
        const float* Wo = (const float*)d_in[8 + 8*l];
        const float* bo = (const float*)d_in[9 + 8*l];
        k_sums<32><<<NIMC/256, 256>>>(W, l);
        k_g<32><<<(BATCH*NN*32 + 255)/256, 256>>>(W, bb, l);
        k_conv<32, false><<<BATCH*BPB, 256>>>(W, Wv, bv, Ww, bw, nullptr);
        k_local<<<BATCH*NN*9, 256, DS_BYTES>>>(Wo, bo);
    }

    const float* Wf  = (const float*)d_in[18];
    const float* bf  = (const float*)d_in[19];
    k_sums<16><<<NIMC/256, 256>>>(Wf, 2);
    k_g<16><<<(BATCH*NN*16 + 255)/256, 256>>>(Wf, bf, 2);
    k_conv<16, true><<<BATCH*BPB, 256>>>(Wf, nullptr, nullptr, nullptr, nullptr, (float*)d_out);
}

// round 17
// speedup vs baseline: 1.3232x; 1.0349x over previous
#include <cuda_runtime.h>
#include <cstdint>

#define NN 48
#define BATCH 4
#define CC 32
#define NSITES (BATCH*NN*NN*NN)
#define TSIZE  ((size_t)NSITES*CC)
#define NIMC   (BATCH*NN*NN*CC)
#define TOTSZ  (BATCH*NN*CC)
#define NPAIR  1176
#define PTH    (NPAIR*NN)
#define BPB    ((PTH + 255)/256)

typedef unsigned long long u64t;

__device__ __forceinline__ u64t f2pack(float lo, float hi) {
    u64t r; asm("mov.b64 %0, {%1, %2};" : "=l"(r) : "f"(lo), "f"(hi)); return r;
}
__device__ __forceinline__ float2 f2unpack(u64t v) {
    float2 r; asm("mov.b64 {%0, %1}, %2;" : "=f"(r.x), "=f"(r.y) : "l"(v)); return r;
}
__device__ __forceinline__ void f2fma(u64t& d, u64t a, u64t b) {
    asm("fma.rn.f32x2 %0, %1, %2, %0;" : "+l"(d) : "l"(a), "l"(b));
}
__device__ __forceinline__ uint32_t smem_u32(const void* p) {
    uint32_t a;
    asm("{ .reg .u64 t; cvta.to.shared.u64 t, %1; cvt.u32.u64 %0, t; }" : "=r"(a) : "l"(p));
    return a;
}
__device__ __forceinline__ void cpa16(uint32_t dst, const void* src) {
    asm volatile("cp.async.cg.shared.global [%0], [%1], 16;" :: "r"(dst), "l"(src) : "memory");
}
#define CP_COMMIT() asm volatile("cp.async.commit_group;" ::: "memory")
#define CP_WAIT(n)  asm volatile("cp.async.wait_group %0;" :: "n"(n) : "memory")

__device__ float g_t[TSIZE];
__device__ float g_v[TSIZE];
__device__ float g_w[TSIZE];
__device__ float g_D [NIMC];      // [b][node][d][m]
__device__ float g_Cc[NIMC];      // [b][node][d][m]
__device__ float g_G [BATCH*NN*CC];
__device__ float g_tot[3*TOTSZ];
__device__ float g_nv[BATCH*NN];
__device__ int   g_cpairs[BATCH*NPAIR];
__device__ int   g_cnt[BATCH];
__device__ int   g_invc[BATCH];

// ---------- mask detect + node_valid + tot zero + compacted pair table ----------
__global__ void k_mask(const void* __restrict__ mask) {
    __shared__ int smode;
    if (threadIdx.x == 0) {
        const unsigned char* mb = (const unsigned char*)mask;
        unsigned char b0 = mb[0], b1 = mb[1];
        int mode;
        if (b0 == 1 && b1 != 0) mode = 0;
        else if (b0 == 1)       mode = 1;
        else                    mode = 2;
        smode = mode;
    }
    if (threadIdx.x < BATCH) { g_cnt[threadIdx.x] = 0; g_invc[threadIdx.x] = 0; }
    __syncthreads();
    int p = threadIdx.x;
    if (p < BATCH*NN) {
        int b = p / NN, i = p % NN;
        size_t idx = (((size_t)b*NN + i)*NN + i)*NN + i;
        int mode = smode;
        float v;
        if (mode == 0)      v = ((const unsigned char*)mask)[idx] ? 1.f : 0.f;
        else if (mode == 1) v = ((const int*)mask)[idx] ? 1.f : 0.f;
        else                v = (((const float*)mask)[idx] != 0.f) ? 1.f : 0.f;
        g_nv[p] = v;
    }
    for (int q = threadIdx.x; q < 3*TOTSZ; q += 1024) g_tot[q] = 0.f;
    __syncthreads();
    for (int q = threadIdx.x; q < BATCH*NPAIR; q += 1024) {
        int b = q / NPAIR, pr = q % NPAIR;
        int i = 0, rem = pr;
        while (rem >= NN - i) { rem -= NN - i; i++; }
        int j = i + rem;
        bool valid = (g_nv[b*NN+i] != 0.f) && (g_nv[b*NN+j] != 0.f);
        int slot;
        if (valid) slot = atomicAdd(&g_cnt[b], 1);
        else       slot = NPAIR - 1 - atomicAdd(&g_invc[b], 1);
        g_cpairs[b*NPAIR + slot] = (i << 8) | j;
    }
}

// ---------- t build (mask fast-path) ----------
__global__ __launch_bounds__(256) void k_build_t(const float* __restrict__ x) {
    int s = blockIdx.x * 256 + threadIdx.x;
    int m = s % NN, j = (s / NN) % NN, i = (s / (NN*NN)) % NN, b = s / (NN*NN*NN);
    float mv = g_nv[b*NN+i] * g_nv[b*NN+j] * g_nv[b*NN+m];
    float4* out = (float4*)(g_t + (size_t)s * CC);
    if (mv == 0.f) {
        float4 z = make_float4(0.f, 0.f, 0.f, 0.f);
#pragma unroll
        for (int q = 0; q < 8; q++) out[q] = z;
        return;
    }
    const float4* xi = (const float4*)(x + (b*NN + i)*CC);
    const float4* xj = (const float4*)(x + (b*NN + j)*CC);
    const float4* xm = (const float4*)(x + (b*NN + m)*CC);
#pragma unroll
    for (int q = 0; q < 8; q++) {
        float4 a = xi[q], c = xj[q], d = xm[q], r;
        r.x = a.x*c.x*d.x; r.y = a.y*c.y*d.y;
        r.z = a.z*c.z*d.z; r.w = a.w*c.w*d.w;
        out[q] = r;
    }
}

// ---------- rows/diag/cols + D/Cc (transposed) + atomic tot; warp-uniform skip ----------
template<int COUT>
__global__ __launch_bounds__(256) void k_sums(const float* __restrict__ W, int layer) {
    __shared__ float sr[8][CC], sd[8][CC], sc[8][CC];
    int p = blockIdx.x * 256 + threadIdx.x;
    int c = p & 31;
    int m = (p >> 5) % NN;
    int a = (p / (32*NN)) % NN;
    int b = p / (32*NN*NN);
    int ls = threadIdx.x >> 5;

    bool valid = (g_nv[b*NN+a] * g_nv[b*NN+m]) != 0.f;
    float rowv = 0.f, diagv = 0.f, colv = 0.f;

    if (valid) {
        const float* pr = g_t + ((((size_t)b*NN + a)*NN + 0)*NN + m)*CC + c;
        float r0=0.f, r1=0.f, r2=0.f, r3=0.f;
#pragma unroll
        for (int j = 0; j < NN; j += 4) {
            r0 += pr[(size_t)(j+0) * (NN*CC)];
            r1 += pr[(size_t)(j+1) * (NN*CC)];
            r2 += pr[(size_t)(j+2) * (NN*CC)];
            r3 += pr[(size_t)(j+3) * (NN*CC)];
        }
        rowv  = (r0+r1+r2+r3) * (1.0f/NN);
        diagv = pr[(size_t)a * (NN*CC)];

        const float* pc = g_t + ((((size_t)b*NN + 0)*NN + a)*NN + m)*CC + c;
        float s0=0.f, s1=0.f, s2=0.f, s3=0.f;
#pragma unroll
        for (int i = 0; i < NN; i += 4) {
            s0 += pc[(size_t)(i+0) * (NN*NN*CC)];
            s1 += pc[(size_t)(i+1) * (NN*NN*CC)];
            s2 += pc[(size_t)(i+2) * (NN*NN*CC)];
            s3 += pc[(size_t)(i+3) * (NN*NN*CC)];
        }
        colv = (s0+s1+s2+s3) * (1.0f/NN);

        atomicAdd(&g_tot[layer*TOTSZ + (b*NN + m)*CC + c], rowv * (1.0f/NN));
    }

    sr[ls][c] = rowv; sd[ls][c] = diagv; sc[ls][c] = colv;
    __syncthreads();

    if (c < COUT) {
        size_t tidx = (((size_t)(b*NN + a))*COUT + c)*NN + m;
        if (valid) {
            float accD = 0.f, accC = 0.f;
#pragma unroll 8
            for (int c2 = 0; c2 < CC; c2++) {
                accD += sd[ls][c2] * __ldg(W + (2*CC + c2)*COUT + c)
                      + sr[ls][c2] * __ldg(W + (3*CC + c2)*COUT + c);
                accC += sc[ls][c2] * __ldg(W + (4*CC + c2)*COUT + c);
            }
            g_D [tidx] = accD;
            g_Cc[tidx] = accC;
        } else {
            g_D [tidx] = 0.f;
            g_Cc[tidx] = 0.f;
        }
    }
}

// ---------- G table, once per conv ----------
template<int COUT>
__global__ __launch_bounds__(256) void k_g(const float* __restrict__ W,
                                           const float* __restrict__ bb, int layer) {
    int q = blockIdx.x * 256 + threadIdx.x;
    if (q >= BATCH*NN*COUT) return;
    int d = q % COUT;
    int mm = (q / COUT) % NN;
    int b = q / (COUT*NN);
    const float* tr = g_tot + layer*TOTSZ + (b*NN + mm)*CC;
    float a = __ldg(bb + d);
#pragma unroll 8
    for (int c = 0; c < CC; c++)
        a += tr[c] * __ldg(W + (5*CC + c)*COUT + d);
    g_G[(b*NN + mm)*CC + d] = a;
}

// ---------- fused snconv: compacted pairs; G staged from precompute ----------
template<int COUT, bool FIN>
__global__ __launch_bounds__(256, 2) void k_conv(const float* __restrict__ W,
                                                 const float* __restrict__ Wv,
                                                 const float* __restrict__ bv,
                                                 const float* __restrict__ Ww,
                                                 const float* __restrict__ bw,
                                                 float* __restrict__ out_final) {
    constexpr int WFL = FIN ? (2*CC*COUT) : (2*CC*COUT + 2*CC*CC);
    constexpr int GST = COUT + 2;
    __shared__ __align__(16) float s[WFL + NN*GST];
    float4* s4 = (float4*)s;

    int bblk = blockIdx.x % BATCH;
    int pblk = blockIdx.x / BATCH;
    int cnt  = g_cnt[bblk];
    bool blk_heavy = (pblk * 256) / NN < cnt;

    if (blk_heavy) {
        {
            const float4* W4 = (const float4*)W;
            if (FIN) {
                for (int idx = threadIdx.x; idx < WFL/4; idx += 256)
                    s4[idx] = W4[idx];
            } else {
                const float4* Wv4 = (const float4*)Wv;
                const float4* Ww4 = (const float4*)Ww;
                for (int idx = threadIdx.x; idx < 1024; idx += 256) {
                    float4 val;
                    if (idx < 512)      val = W4[idx];
                    else if (idx < 768) val = Wv4[idx - 512];
                    else                val = Ww4[idx - 768];
                    s4[idx] = val;
                }
            }
        }
        for (int idx = threadIdx.x; idx < NN*COUT; idx += 256) {
            int mm = idx / COUT, d = idx % COUT;
            s[WFL + mm*GST + d] = g_G[(bblk*NN + mm)*CC + d];
        }
        __syncthreads();
    }

    int local = pblk * 256 + threadIdx.x;
    if (local >= PTH) return;
    int m  = local % NN;
    int pr = local / NN;
    int pij = g_cpairs[bblk*NPAIR + pr];
    int i = pij >> 8, j = pij & 255;

    size_t s0 = (((size_t)bblk*NN + i)*NN + j)*NN + m;
    size_t s1 = (((size_t)bblk*NN + j)*NN + i)*NN + m;

    float mv = g_nv[bblk*NN+i] * g_nv[bblk*NN+j] * g_nv[bblk*NN+m];

    if (mv == 0.f) {
        if (FIN) {
            ulonglong2 z = make_ulonglong2(0ULL, 0ULL);
            ulonglong2* op0 = (ulonglong2*)(out_final + s0 * COUT);
            ulonglong2* op1 = (ulonglong2*)(out_final + s1 * COUT);
#pragma unroll
            for (int q = 0; q < COUT/4; q++) { op0[q] = z; op1[q] = z; }
        } else {
            const ulonglong2* bv2 = (const ulonglong2*)bv;
            const ulonglong2* bw2 = (const ulonglong2*)bw;
            ulonglong2* v0 = (ulonglong2*)(g_v + s0*CC);
            ulonglong2* v1 = (ulonglong2*)(g_v + s1*CC);
            ulonglong2* w0 = (ulonglong2*)(g_w + s0*CC);
            ulonglong2* w1 = (ulonglong2*)(g_w + s1*CC);
#pragma unroll
            for (int q = 0; q < CC/4; q++) {
                ulonglong2 a = __ldg(bv2 + q);
                ulonglong2 b2 = __ldg(bw2 + q);
                v0[q] = a; v1[q] = a;
                w0[q] = b2; w1[q] = b2;
            }
        }
        return;
    }

    const float* tv0 = g_t + s0 * CC;
    const float* tv1 = g_t + s1 * CC;

    u64t acc0[COUT/2], acc1[COUT/2];
#pragma unroll
    for (int q = 0; q < COUT/2; q++) { acc0[q] = 0ULL; acc1[q] = 0ULL; }

#pragma unroll 1
    for (int c0 = 0; c0 < CC; c0 += 8) {
        float ta[8], tb[8];
        float4 q4;
        q4 = *(const float4*)(tv0 + c0);     ta[0]=q4.x; ta[1]=q4.y; ta[2]=q4.z; ta[3]=q4.w;
        q4 = *(const float4*)(tv0 + c0 + 4); ta[4]=q4.x; ta[5]=q4.y; ta[6]=q4.z; ta[7]=q4.w;
        q4 = *(const float4*)(tv1 + c0);     tb[0]=q4.x; tb[1]=q4.y; tb[2]=q4.z; tb[3]=q4.w;
        q4 = *(const float4*)(tv1 + c0 + 4); tb[4]=q4.x; tb[5]=q4.y; tb[6]=q4.z; tb[7]=q4.w;
#pragma unroll
        for (int cc = 0; cc < 8; cc++) {
            int c = c0 + cc;
            u64t ta2 = f2pack(ta[cc], ta[cc]);
            u64t tb2 = f2pack(tb[cc], tb[cc]);
            const ulonglong2* w0p = (const ulonglong2*)(s + c*COUT);
            const ulonglong2* w1p = (const ulonglong2*)(s + CC*COUT + c*COUT);
#pragma unroll
            for (int q = 0; q < COUT/4; q++) {
                ulonglong2 w0 = w0p[q];
                ulonglong2 w1 = w1p[q];
                f2fma(acc0[2*q+0], ta2, w0.x);
                f2fma(acc0[2*q+1], ta2, w0.y);
                f2fma(acc0[2*q+0], tb2, w1.x);
                f2fma(acc0[2*q+1], tb2, w1.y);
                f2fma(acc1[2*q+0], tb2, w0.x);
                f2fma(acc1[2*q+1], tb2, w0.y);
                f2fma(acc1[2*q+0], ta2, w1.x);
                f2fma(acc1[2*q+1], ta2, w1.y);
            }
        }
    }

    const float* Dib = g_D  + (((size_t)(bblk*NN + i))*COUT)*NN + m;
    const float* Djb = g_D  + (((size_t)(bblk*NN + j))*COUT)*NN + m;
    const float* Cib = g_Cc + (((size_t)(bblk*NN + i))*COUT)*NN + m;
    const float* Cjb = g_Cc + (((size_t)(bblk*NN + j))*COUT)*NN + m;
    const float* Gs  = s + WFL + m*GST;
#pragma unroll
    for (int q = 0; q < COUT/2; q++) {
        int d0 = 2*q, d1 = 2*q+1;
        float2 a0 = f2unpack(acc0[q]);
        float2 a1 = f2unpack(acc1[q]);
        float g0 = Gs[d0],        g1 = Gs[d1];
        float di0 = Dib[d0*NN],   di1 = Dib[d1*NN];
        float dj0 = Djb[d0*NN],   dj1 = Djb[d1*NN];
        float ci0 = Cib[d0*NN],   ci1 = Cib[d1*NN];
        float cj0 = Cjb[d0*NN],   cj1 = Cjb[d1*NN];
        a0.x = (a0.x + di0 + cj0 + g0) * mv;
        a0.y = (a0.y + di1 + cj1 + g1) * mv;
        a1.x = (a1.x + dj0 + ci0 + g0) * mv;
        a1.y = (a1.y + dj1 + ci1 + g1) * mv;
        acc0[q] = f2pack(a0.x, a0.y);
        acc1[q] = f2pack(a1.x, a1.y);
    }

    if (FIN) {
        ulonglong2* op0 = (ulonglong2*)(out_final + s0 * COUT);
        ulonglong2* op1 = (ulonglong2*)(out_final + s1 * COUT);
#pragma unroll
        for (int q = 0; q < COUT/4; q++) {
            op0[q] = make_ulonglong2(acc0[2*q], acc0[2*q+1]);
            op1[q] = make_ulonglong2(acc1[2*q], acc1[2*q+1]);
        }
    } else {
        const int WVF = 2048, WWF = 3072;
#pragma unroll 1
        for (int pass = 0; pass < 2; pass++) {
            const int WF = pass ? WWF : WVF;
            const float* bias = pass ? bw : bv;
            float* outg = pass ? g_w : g_v;
#pragma unroll 1
            for (int half = 0; half < 2; half++) {
                u64t p0[8], p1[8];
                const u64t* b2 = (const u64t*)(bias + half*16);
#pragma unroll
                for (int e = 0; e < 8; e++) { u64t bb2 = b2[e]; p0[e] = bb2; p1[e] = bb2; }
#pragma unroll 1
                for (int dq = 0; dq < COUT/2; dq++) {
                    float2 a0 = f2unpack(acc0[dq]);
                    float2 a1 = f2unpack(acc1[dq]);
                    u64t a0x = f2pack(a0.x, a0.x), a0y = f2pack(a0.y, a0.y);
                    u64t a1x = f2pack(a1.x, a1.x), a1y = f2pack(a1.y, a1.y);
                    const ulonglong2* r0 = (const ulonglong2*)(s + WF + (2*dq+0)*CC + half*16);
                    const ulonglong2* r1 = (const ulonglong2*)(s + WF + (2*dq+1)*CC + half*16);
#pragma unroll
                    for (int q = 0; q < 4; q++) {
                        ulonglong2 w0 = r0[q];
                        ulonglong2 w1 = r1[q];
                        f2fma(p0[2*q+0], a0x, w0.x); f2fma(p0[2*q+1], a0x, w0.y);
                        f2fma(p0[2*q+0], a0y, w1.x); f2fma(p0[2*q+1], a0y, w1.y);
                        f2fma(p1[2*q+0], a1x, w0.x); f2fma(p1[2*q+1], a1x, w0.y);
                        f2fma(p1[2*q+0], a1y, w1.x); f2fma(p1[2*q+1], a1y, w1.y);
                    }
                }
                ulonglong2* o0 = (ulonglong2*)(outg + s0*CC + half*16);
                ulonglong2* o1 = (ulonglong2*)(outg + s1*CC + half*16);
#pragma unroll
                for (int q = 0; q < 4; q++) {
                    o0[q] = make_ulonglong2(p0[2*q], p0[2*q+1]);
                    o1[q] = make_ulonglong2(p1[2*q], p1[2*q+1]);
                }
            }
        }
    }
}

// ---------- localconv: block-level mask skip + cp.async double-buffered K ----------
#define LK 12
#define VS_FL (16*LK*32)
#define WS_J_STRIDE 109
#define WS_FL (16*WS_J_STRIDE*4)
#define BUF_FL (VS_FL + WS_FL)
#define WO_OFFL (2*BUF_FL)
#define DS_BYTES ((WO_OFFL + 1024)*4)
#define ZST 34

__global__ __launch_bounds__(256) void k_local(const float* __restrict__ Wo,
                                               const float* __restrict__ bo) {
    extern __shared__ __align__(16) float sm[];
    float* wo = sm + WO_OFFL;
    float* zs = sm;

    int blk = blockIdx.x;
    int q9 = blk % 9;
    int it3 = q9 / 3, jt3 = q9 % 3;
    int m = (blk / 9) % NN, b = blk / (9*NN);
    int i0 = it3 * 16, j0 = jt3 * 16;
    int tid = threadIdx.x;
    uint32_t smbase = smem_u32(sm);

    // ---- block-level mask skip: all outputs zero if m invalid or a full tile invalid ----
    {
        float nm = g_nv[b*NN + m];
        float ai = 0.f, aj = 0.f;
#pragma unroll
        for (int q = 0; q < 16; q++) {
            ai += g_nv[b*NN + i0 + q];
            aj += g_nv[b*NN + j0 + q];
        }
        if (nm == 0.f || ai == 0.f || aj == 0.f) {
            int site = tid;
            int il = site >> 4, jl = site & 15;
            float4* op = (float4*)(g_t + ((((size_t)b*NN + i0+il)*NN + j0+jl)*NN + m)*CC);
            float4 z = make_float4(0.f, 0.f, 0.f, 0.f);
#pragma unroll
            for (int q = 0; q < 8; q++) op[q] = z;
            return;
        }
    }

    ((float4*)wo)[tid] = __ldg(((const float4*)Wo) + tid);

    auto load_chunk = [&](int kc, int bi) {
        uint32_t vb = smbase + (bi*BUF_FL)*4;
        uint32_t wb = vb + VS_FL*4;
        for (int idx = tid; idx < 16*LK*8; idx += 256) {
            int r = idx >> 3, c4 = idx & 7;
            int iiL = r / LK, k = r % LK;
            const float* src = g_v + ((((size_t)b*NN + i0+iiL)*NN + kc*LK + k)*NN + m)*CC + c4*4;
            cpa16(vb + ((iiL*LK + k)*8 + c4)*16, src);
        }
        for (int idx = tid; idx < 16*LK*8; idx += 256) {
            int r = idx >> 3, c4 = idx & 7;
            int jjL = r / LK, k = r % LK;
            const float* src = g_w + ((((size_t)b*NN + kc*LK + k)*NN + j0+jjL)*NN + m)*CC + c4*4;
            cpa16(wb + (jjL*WS_J_STRIDE + k*9 + c4)*16, src);
        }
    };

    int ct = tid & 7, jt = (tid >> 3) & 7, it = tid >> 6;
    u64t acc[4][2][2];
#pragma unroll
    for (int r = 0; r < 4; r++)
#pragma unroll
        for (int d = 0; d < 2; d++) { acc[r][d][0] = 0ULL; acc[r][d][1] = 0ULL; }

    load_chunk(0, 0);
    CP_COMMIT();

#pragma unroll 1
    for (int kc = 0; kc < 4; kc++) {
        int bi = kc & 1;
        if (kc + 1 < 4) { load_chunk(kc + 1, (kc + 1) & 1); CP_COMMIT(); }
        if (kc + 1 < 4) { CP_WAIT(1); } else { CP_WAIT(0); }
        __syncthreads();

        const float* vs = sm + bi*BUF_FL;
        const float* ws = vs + VS_FL;
#pragma unroll 4
        for (int k = 0; k < LK; k++) {
            ulonglong2 v[4];
#pragma unroll
            for (int r = 0; r < 4; r++)
                v[r] = *((const ulonglong2*)vs + ((it*4+r)*LK + k)*8 + ct);
            ulonglong2 w[2];
#pragma unroll
            for (int d = 0; d < 2; d++)
                w[d] = *((const ulonglong2*)ws + (jt*2+d)*WS_J_STRIDE + k*9 + ct);
#pragma unroll
            for (int r = 0; r < 4; r++)
#pragma unroll
                for (int d = 0; d < 2; d++) {
                    f2fma(acc[r][d][0], v[r].x, w[d].x);
                    f2fma(acc[r][d][1], v[r].y, w[d].y);
                }
        }
        __syncthreads();
    }

#pragma unroll
    for (int r = 0; r < 4; r++)
#pragma unroll
        for (int d = 0; d < 2; d++) {
            int il = it*4 + r, jl = jt*2 + d;
            u64t* zp = (u64t*)(zs + (il*16 + jl)*ZST + ct*4);
            zp[0] = acc[r][d][0];
            zp[1] = acc[r][d][1];
        }
    __syncthreads();

    int site = tid;
    int il = site >> 4, jl = site & 15;
    int gi = i0 + il, gj = j0 + jl;
    u64t oa[16];
#pragma unroll
    for (int q = 0; q < 16; q++) oa[q] = 0ULL;
#pragma unroll 4
    for (int c = 0; c < 32; c++) {
        float zv = zs[site*ZST + c];
        u64t zv2 = f2pack(zv, zv);
        const ulonglong2* wrow = (const ulonglong2*)(wo + c*32);
#pragma unroll
        for (int q = 0; q < 8; q++) {
            ulonglong2 w = wrow[q];
            f2fma(oa[2*q+0], zv2, w.x);
            f2fma(oa[2*q+1], zv2, w.y);
        }
    }
    float mv = g_nv[b*NN+gi] * g_nv[b*NN+gj] * g_nv[b*NN+m];
    float* op = g_t + ((((size_t)b*NN + gi)*NN + gj)*NN + m)*CC;
#pragma unroll
    for (int q = 0; q < 8; q++) {
        float2 p0 = f2unpack(oa[2*q+0]);
        float2 p1 = f2unpack(oa[2*q+1]);
        float e0 = p0.x * (1.0f/NN) + __ldg(bo + 4*q+0);
        float e1 = p0.y * (1.0f/NN) + __ldg(bo + 4*q+1);
        float e2 = p1.x * (1.0f/NN) + __ldg(bo + 4*q+2);
        float e3 = p1.y * (1.0f/NN) + __ldg(bo + 4*q+3);
        e0 = (e0 > 0.f ? e0 : 0.f) * mv;
        e1 = (e1 > 0.f ? e1 : 0.f) * mv;
        e2 = (e2 > 0.f ? e2 : 0.f) * mv;
        e3 = (e3 > 0.f ? e3 : 0.f) * mv;
        *(float4*)(op + 4*q) = make_float4(e0, e1, e2, e3);
    }
}

// ---------- host ----------
extern "C" void kernel_launch(void* const* d_in, const int* in_sizes, int n_in,
                              void* d_out, int out_size) {
    (void)in_sizes; (void)n_in; (void)out_size;
    const float* x    = (const float*)d_in[0];
    const void*  mask = d_in[1];

    cudaFuncSetAttribute(k_local, cudaFuncAttributeMaxDynamicSharedMemorySize, DS_BYTES);

    k_mask<<<1, 1024>>>(mask);
    k_build_t<<<NSITES/256, 256>>>(x);

    for (int l = 0; l < 2; l++) {
        const float* W  = (const float*)d_in[2 + 8*l];
        const float* bb = (const float*)d_in[3 + 8*l];
        const float* Wv = (const float*)d_in[4 + 8*l];
        const float* bv = (const float*)d_in[5 + 8*l];
        const float* Ww = (const float*)d_in[6 + 8*l];
        const float* bw = (const float*)d_in[7 + 8*l];
        const float* Wo = (const float*)d_in[8 + 8*l];
        const float* bo = (const float*)d_in[9 + 8*l];
        k_sums<32><<<NIMC/256, 256>>>(W, l);
        k_g<32><<<(BATCH*NN*32 + 255)/256, 256>>>(W, bb, l);
        k_conv<32, false><<<BATCH*BPB, 256>>>(W, Wv, bv, Ww, bw, nullptr);
        k_local<<<BATCH*NN*9, 256, DS_BYTES>>>(Wo, bo);
    }

    const float* Wf  = (const float*)d_in[18];
    const float* bf  = (const float*)d_in[19];
    k_sums<16><<<NIMC/256, 256>>>(Wf, 2);
    k_g<16><<<(BATCH*NN*16 + 255)/256, 256>>>(Wf, bf, 2);
    k_conv<16, true><<<BATCH*BPB, 256>>>(Wf, nullptr, nullptr, nullptr, nullptr, (float*)d_out);
}